// round 13
// baseline (speedup 1.0000x reference)
#include <cuda_runtime.h>
#include <cuda_bf16.h>
#include <cstdint>
#include <math.h>

#define D_MODEL 2048
#define T_SEQ   2048
#define N_HEADS 16
#define D_HEAD  128
#define BT_MAX  4096   // B=2 * T=2048

// ---------------- scratch (device globals; allocation-free) ----------------
__device__ float g_q[(size_t)BT_MAX * D_MODEL];
__device__ float g_k[(size_t)BT_MAX * D_MODEL];
__device__ float g_attn[(size_t)BT_MAX * D_MODEL];

__device__ __nv_bfloat16 g_qh[(size_t)BT_MAX * D_MODEL];       // Q hi (scaled)
__device__ __nv_bfloat16 g_ql[(size_t)BT_MAX * D_MODEL];
__device__ __nv_bfloat16 g_kh[(size_t)BT_MAX * D_MODEL];       // K hi
__device__ __nv_bfloat16 g_kl[(size_t)BT_MAX * D_MODEL];
__device__ __nv_bfloat16 g_vh[(size_t)BT_MAX * D_MODEL];       // V hi
__device__ __nv_bfloat16 g_vl[(size_t)BT_MAX * D_MODEL];

__device__ int8_t g_xq0[(size_t)BT_MAX * D_MODEL];
__device__ int8_t g_xq1[(size_t)BT_MAX * D_MODEL];
__device__ int8_t g_wq0[(size_t)4 * D_MODEL * D_MODEL];
__device__ int8_t g_wq1[(size_t)4 * D_MODEL * D_MODEL];
__device__ int8_t g_aq0[(size_t)BT_MAX * D_MODEL];
__device__ int8_t g_aq1[(size_t)BT_MAX * D_MODEL];
__device__ float  g_xs[BT_MAX];
__device__ float  g_ws[4 * D_MODEL];
__device__ float  g_as[BT_MAX];

__device__ __forceinline__ uint32_t smem_u32(const void* p) {
    uint32_t a;
    asm("{ .reg .u64 t; cvta.to.shared.u64 t, %1; cvt.u32.u64 %0, t; }" : "=r"(a) : "l"(p));
    return a;
}

__device__ __forceinline__ void mma_bf16(float* c, uint32_t a0, uint32_t a1,
                                         uint32_t a2, uint32_t a3,
                                         uint32_t b0, uint32_t b1) {
    asm volatile(
        "mma.sync.aligned.m16n8k16.row.col.f32.bf16.bf16.f32 "
        "{%0,%1,%2,%3}, {%4,%5,%6,%7}, {%8,%9}, {%0,%1,%2,%3};"
        : "+f"(c[0]), "+f"(c[1]), "+f"(c[2]), "+f"(c[3])
        : "r"(a0), "r"(a1), "r"(a2), "r"(a3), "r"(b0), "r"(b1));
}

__device__ __forceinline__ void mma_i8(int* c, const uint32_t* a,
                                       uint32_t b0, uint32_t b1) {
    asm volatile(
        "mma.sync.aligned.m16n8k32.row.col.s32.s8.s8.s32 "
        "{%0,%1,%2,%3}, {%4,%5,%6,%7}, {%8,%9}, {%0,%1,%2,%3};"
        : "+r"(c[0]), "+r"(c[1]), "+r"(c[2]), "+r"(c[3])
        : "r"(a[0]), "r"(a[1]), "r"(a[2]), "r"(a[3]), "r"(b0), "r"(b1));
}

#define LDSM4(r, a) asm volatile(                                                  \
    "ldmatrix.sync.aligned.m8n8.x4.shared.b16 {%0,%1,%2,%3}, [%4];"                \
    : "=r"((r)[0]), "=r"((r)[1]), "=r"((r)[2]), "=r"((r)[3]) : "r"(a))

#define LDSM4T(r, a) asm volatile(                                                 \
    "ldmatrix.sync.aligned.m8n8.x4.trans.shared.b16 {%0,%1,%2,%3}, [%4];"          \
    : "=r"((r)[0]), "=r"((r)[1]), "=r"((r)[2]), "=r"((r)[3]) : "r"(a))

__device__ __forceinline__ float ex2f(float x) {
    float r;
    asm("ex2.approx.f32 %0, %1;" : "=f"(r) : "f"(x));
    return r;
}

// ---------------- per-row int8 quantization: A = s*(q0 + q1/128) ----------------
__device__ __forceinline__ void quant_row_body(
    const float* __restrict__ p, int8_t* __restrict__ q0,
    int8_t* __restrict__ q1, float* __restrict__ scale, int srow)
{
    const int tid = threadIdx.x;
    float4 v[2];
    float mx = 0.f;
#pragma unroll
    for (int i = 0; i < 2; i++) {
        float4 t = ((const float4*)p)[tid + i * 256];
        v[i] = t;
        mx = fmaxf(mx, fmaxf(fmaxf(fabsf(t.x), fabsf(t.y)),
                             fmaxf(fabsf(t.z), fabsf(t.w))));
    }
#pragma unroll
    for (int o = 16; o > 0; o >>= 1) mx = fmaxf(mx, __shfl_xor_sync(0xffffffffu, mx, o));
    __shared__ float red[8];
    __shared__ float s_inv, s_val;
    if ((tid & 31) == 0) red[tid >> 5] = mx;
    __syncthreads();
    if (tid == 0) {
        float m = red[0];
#pragma unroll
        for (int i = 1; i < 8; i++) m = fmaxf(m, red[i]);
        m = fmaxf(m, 1e-30f);
        s_inv = 127.0f / m;
        s_val = m * (1.0f / 127.0f);
    }
    __syncthreads();
    const float si = s_inv;

#pragma unroll
    for (int i = 0; i < 2; i++) {
        float t0 = v[i].x * si, t1 = v[i].y * si, t2 = v[i].z * si, t3 = v[i].w * si;
        int a0 = __float2int_rn(t0), a1 = __float2int_rn(t1);
        int a2 = __float2int_rn(t2), a3 = __float2int_rn(t3);
        int b0 = __float2int_rn((t0 - a0) * 128.f);
        int b1 = __float2int_rn((t1 - a1) * 128.f);
        int b2 = __float2int_rn((t2 - a2) * 128.f);
        int b3 = __float2int_rn((t3 - a3) * 128.f);
        char4 c0 = make_char4((signed char)a0, (signed char)a1,
                              (signed char)a2, (signed char)a3);
        char4 c1 = make_char4((signed char)b0, (signed char)b1,
                              (signed char)b2, (signed char)b3);
        ((char4*)q0)[tid + i * 256] = c0;
        ((char4*)q1)[tid + i * 256] = c1;
    }
    if (tid == 0) scale[srow] = s_val;
}

__global__ __launch_bounds__(256) void quant_rows(
    const float* __restrict__ src, int8_t* __restrict__ q0,
    int8_t* __restrict__ q1, float* __restrict__ scale)
{
    const int row = blockIdx.x;
    quant_row_body(src + (size_t)row * D_MODEL,
                   q0 + (size_t)row * D_MODEL,
                   q1 + (size_t)row * D_MODEL, scale, row);
}

__global__ __launch_bounds__(256) void quant_w4(
    const float* __restrict__ w0, const float* __restrict__ w1,
    const float* __restrict__ w2, const float* __restrict__ w3,
    int8_t* __restrict__ q0, int8_t* __restrict__ q1, float* __restrict__ scale)
{
    const int row = blockIdx.x, y = blockIdx.y;
    const float* src = (y == 0) ? w0 : (y == 1) ? w1 : (y == 2) ? w2 : w3;
    size_t off = (size_t)y * D_MODEL * D_MODEL + (size_t)row * D_MODEL;
    quant_row_body(src + (size_t)row * D_MODEL, q0 + off, q1 + off,
                   scale, y * D_MODEL + row);
}

// ---------------- int8 emulated GEMM: C = A @ W^T + bias ----------------
// CTA 128x128, warp tile 64x32 (2x4 warps). k-tile 32 int8.
#define IM 128
#define IN 128
#define IROW 48                      // 32 data bytes + 16 pad per row
#define IREG (IM * IROW)             // 6144 B per slice region
#define ISTAGE (4 * IREG)            // A0,A1,B0,B1 = 24576 B
#define ISTAGES 4
#define I8_SMEM (ISTAGES * ISTAGE)   // 98304 B

__global__ __launch_bounds__(256) void gemm_i8(
    const int8_t* __restrict__ Aq0, const int8_t* __restrict__ Aq1,
    const float* __restrict__ As,
    const int8_t* __restrict__ Wq0, const int8_t* __restrict__ Wq1,
    const float* __restrict__ Ws,
    const float* __restrict__ bias0, float* __restrict__ C0,
    const float* __restrict__ bias1, float* __restrict__ C1,
    const float* __restrict__ bias2,
    __nv_bfloat16* __restrict__ Vh, __nv_bfloat16* __restrict__ Vl,
    int M, int N, int K)
{
    extern __shared__ int8_t ismem[];
    const int tid = threadIdx.x;
    const int bz = blockIdx.z;
    const int8_t* Bq0 = Wq0 + (size_t)bz * D_MODEL * D_MODEL;
    const int8_t* Bq1 = Wq1 + (size_t)bz * D_MODEL * D_MODEL;
    const float*  Wsp = Ws + bz * D_MODEL;
    const float* bia = (bz == 0) ? bias0 : (bz == 1) ? bias1 : bias2;
    float*       C   = (bz == 0) ? C0 : C1;

    const int m0 = blockIdx.y * IM;
    const int n0 = blockIdx.x * IN;
    const int NTILES = K / 32;   // 64

    const uint32_t sbase = smem_u32(ismem);

    // load mapping: 1024 16B-chunks per stage, 4 per thread
    const int8_t* gsrc[4];
    uint32_t soff[4];
#pragma unroll
    for (int i = 0; i < 4; i++) {
        int c = tid + i * 256;
        if (c < 512) {
            int slice = c >> 8, m = c & 255, row = m >> 1, half = m & 1;
            gsrc[i] = (slice ? Aq1 : Aq0) + (size_t)(m0 + row) * K + half * 16;
            soff[i] = (uint32_t)(slice * IREG + row * IROW + half * 16);
        } else {
            int cb = c - 512;
            int slice = cb >> 8, m = cb & 255, row = m >> 1, half = m & 1;
            gsrc[i] = (slice ? Bq1 : Bq0) + (size_t)(n0 + row) * K + half * 16;
            soff[i] = (uint32_t)(2 * IREG + slice * IREG + row * IROW + half * 16);
        }
    }

#define ILOAD(t, s) do {                                                         \
        uint32_t _sb = sbase + (uint32_t)((s) * ISTAGE);                         \
        size_t _go = (size_t)(t) * 32;                                           \
        _Pragma("unroll")                                                        \
        for (int _i = 0; _i < 4; _i++) {                                         \
            asm volatile("cp.async.cg.shared.global [%0], [%1], 16;"             \
                :: "r"(_sb + soff[_i]), "l"(gsrc[_i] + _go));                    \
        } } while (0)

    const int warp = tid >> 5, lane = tid & 31;
    const int wm = (warp >> 2) * 64, wn = (warp & 3) * 32;
    const int g = lane >> 2, tg = lane & 3;

    const uint32_t aLane = (uint32_t)((wm + (lane & 15)) * IROW + ((lane >> 4) & 1) * 16);
    const uint32_t bLane = (uint32_t)(2 * IREG
                         + (wn + (lane & 7) + ((lane & 16) ? 8 : 0)) * IROW
                         + ((lane & 8) ? 16 : 0));

    int cM[4][4][4], cX[4][4][4];
#pragma unroll
    for (int mi = 0; mi < 4; mi++)
#pragma unroll
        for (int ni = 0; ni < 4; ni++)
#pragma unroll
            for (int r = 0; r < 4; r++) { cM[mi][ni][r] = 0; cX[mi][ni][r] = 0; }

    ILOAD(0, 0);
    asm volatile("cp.async.commit_group;" ::: "memory");
    ILOAD(1, 1);
    asm volatile("cp.async.commit_group;" ::: "memory");
    ILOAD(2, 2);
    asm volatile("cp.async.commit_group;" ::: "memory");

    for (int kt = 0; kt < NTILES; kt++) {
        asm volatile("cp.async.wait_group 2;" ::: "memory");
        __syncthreads();

        int lt = kt + 3;
        if (lt < NTILES) ILOAD(lt, lt & 3);
        asm volatile("cp.async.commit_group;" ::: "memory");

        const uint32_t stb = sbase + (uint32_t)((kt & 3) * ISTAGE);
        const uint32_t aB = stb + aLane;
        const uint32_t bB = stb + bLane;

        uint32_t a0f[4][4], a1f[4][4];
#pragma unroll
        for (int mi = 0; mi < 4; mi++) {
            uint32_t ad = aB + (uint32_t)(mi * 16 * IROW);
            LDSM4(a0f[mi], ad);
            LDSM4(a1f[mi], ad + (uint32_t)IREG);
        }
        uint32_t b0f[2][4], b1f[2][4];
#pragma unroll
        for (int p = 0; p < 2; p++) {
            uint32_t bd = bB + (uint32_t)(p * 16 * IROW);
            LDSM4(b0f[p], bd);
            LDSM4(b1f[p], bd + (uint32_t)IREG);
        }
#pragma unroll
        for (int mi = 0; mi < 4; mi++)
#pragma unroll
            for (int p = 0; p < 2; p++)
#pragma unroll
                for (int hf = 0; hf < 2; hf++) {
                    int ni = 2 * p + hf;
                    mma_i8(cM[mi][ni], a0f[mi], b0f[p][2 * hf], b0f[p][2 * hf + 1]);
                    mma_i8(cX[mi][ni], a0f[mi], b1f[p][2 * hf], b1f[p][2 * hf + 1]);
                    mma_i8(cX[mi][ni], a1f[mi], b0f[p][2 * hf], b0f[p][2 * hf + 1]);
                }
    }

    // ---- epilogue: scales + bias ----
#pragma unroll
    for (int ni = 0; ni < 4; ni++) {
        int col = n0 + wn + ni * 8 + 2 * tg;
        float2 bb = *(const float2*)(bia + col);
        float sc0 = Wsp[col], sc1 = Wsp[col + 1];
#pragma unroll
        for (int mi = 0; mi < 4; mi++) {
            int row = m0 + wm + mi * 16 + g;
            float sa0 = As[row], sa1 = As[row + 8];
            float f00 = sa0 * sc0 * ((float)cM[mi][ni][0]
                      + (float)cX[mi][ni][0] * 0.0078125f) + bb.x;
            float f01 = sa0 * sc1 * ((float)cM[mi][ni][1]
                      + (float)cX[mi][ni][1] * 0.0078125f) + bb.y;
            float f10 = sa1 * sc0 * ((float)cM[mi][ni][2]
                      + (float)cX[mi][ni][2] * 0.0078125f) + bb.x;
            float f11 = sa1 * sc1 * ((float)cM[mi][ni][3]
                      + (float)cX[mi][ni][3] * 0.0078125f) + bb.y;
            if (bz == 2) {
                __nv_bfloat162 h0 = __floats2bfloat162_rn(f00, f01);
                __nv_bfloat162 l0 = __floats2bfloat162_rn(
                    f00 - __bfloat162float(h0.x), f01 - __bfloat162float(h0.y));
                __nv_bfloat162 h1 = __floats2bfloat162_rn(f10, f11);
                __nv_bfloat162 l1 = __floats2bfloat162_rn(
                    f10 - __bfloat162float(h1.x), f11 - __bfloat162float(h1.y));
                *(__nv_bfloat162*)(Vh + (size_t)row * N + col) = h0;
                *(__nv_bfloat162*)(Vl + (size_t)row * N + col) = l0;
                *(__nv_bfloat162*)(Vh + (size_t)(row + 8) * N + col) = h1;
                *(__nv_bfloat162*)(Vl + (size_t)(row + 8) * N + col) = l1;
            } else {
                *(float2*)(C + (size_t)row * N + col) = make_float2(f00, f01);
                *(float2*)(C + (size_t)(row + 8) * N + col) = make_float2(f10, f11);
            }
        }
    }
#undef ILOAD
}

// ---------------- fused RMSNorm + RoPE -> bf16 hi/lo; blockIdx.y: 0=Q, 1=K ----------------
__global__ __launch_bounds__(256) void rmsnorm_rope_bf(
    const float* __restrict__ qsrc, const float* __restrict__ ksrc,
    const float* __restrict__ qw, const float* __restrict__ kw,
    const float* __restrict__ cosb, const float* __restrict__ sinb,
    __nv_bfloat16* __restrict__ qoh, __nv_bfloat16* __restrict__ qol,
    __nv_bfloat16* __restrict__ koh, __nv_bfloat16* __restrict__ kol,
    float qscale)
{
    const int which = blockIdx.y;
    const float* hsrc = which ? ksrc : qsrc;
    const float* w    = which ? kw   : qw;
    __nv_bfloat16* oh = which ? koh  : qoh;
    __nv_bfloat16* ol = which ? kol  : qol;
    const float outscale = which ? 1.0f : qscale;

    const int row = blockIdx.x;
    const int t = row & (T_SEQ - 1);
    const float* hp = hsrc + (size_t)row * D_MODEL;
    const float* cp = cosb + (size_t)t * D_MODEL;
    const float* sp = sinb + (size_t)t * D_MODEL;
    const int tid = threadIdx.x;

    float4 vals[2];
    float ss = 0.f;
#pragma unroll
    for (int i = 0; i < 2; i++) {
        float4 v = ((const float4*)hp)[tid + i * 256];
        vals[i] = v;
        ss += v.x * v.x + v.y * v.y + v.z * v.z + v.w * v.w;
    }
#pragma unroll
    for (int o = 16; o > 0; o >>= 1) ss += __shfl_xor_sync(0xffffffffu, ss, o);
    __shared__ float red[8];
    __shared__ float s_inv;
    if ((tid & 31) == 0) red[tid >> 5] = ss;
    __syncthreads();
    if (tid == 0) {
        float tot = 0.f;
#pragma unroll
        for (int i = 0; i < 8; i++) tot += red[i];
        s_inv = rsqrtf(tot * (1.0f / D_MODEL) + 1e-6f);
    }
    __syncthreads();
    const float inv = s_inv;

#pragma unroll
    for (int i = 0; i < 2; i++) {
        int fi = tid + i * 256;
        float4 v = vals[i];
        float4 wv = ((const float4*)w)[fi];
        float4 c4 = ((const float4*)cp)[fi];
        float4 s4 = ((const float4*)sp)[fi];
        float nx = v.x * inv * wv.x;
        float ny = v.y * inv * wv.y;
        float nz = v.z * inv * wv.z;
        float nw = v.w * inv * wv.w;
        float o0 = (nx * c4.x - ny * s4.x) * outscale;
        float o1 = (ny * c4.y + nx * s4.y) * outscale;
        float o2 = (nz * c4.z - nw * s4.z) * outscale;
        float o3 = (nw * c4.w + nz * s4.w) * outscale;
        __nv_bfloat16 h0 = __float2bfloat16(o0), h1 = __float2bfloat16(o1);
        __nv_bfloat16 h2 = __float2bfloat16(o2), h3 = __float2bfloat16(o3);
        __nv_bfloat16 l0 = __float2bfloat16(o0 - __bfloat162float(h0));
        __nv_bfloat16 l1 = __float2bfloat16(o1 - __bfloat162float(h1));
        __nv_bfloat16 l2 = __float2bfloat16(o2 - __bfloat162float(h2));
        __nv_bfloat16 l3 = __float2bfloat16(o3 - __bfloat162float(h3));
        __nv_bfloat162* hp2 = (__nv_bfloat162*)(oh + (size_t)row * D_MODEL + fi * 4);
        __nv_bfloat162* lp2 = (__nv_bfloat162*)(ol + (size_t)row * D_MODEL + fi * 4);
        hp2[0] = __nv_bfloat162(h0, h1); hp2[1] = __nv_bfloat162(h2, h3);
        lp2[0] = __nv_bfloat162(l0, l1); lp2[1] = __nv_bfloat162(l2, l3);
    }
}

// ---------------- tensor-core flash attention (3xBF16, 2 CTAs/SM) ----------------
#define AQ 64
#define AK 64
#define KSTR 136
#define K_ELEMS (AK * KSTR)
#define KSTAGE (2 * K_ELEMS)
#define V_BASE (2 * KSTAGE)
#define ATTN_ELEMS (V_BASE + 2 * K_ELEMS)
#define ATTN_SMEM (ATTN_ELEMS * 2)           // 104448 B

__global__ __launch_bounds__(128, 2) void attn_tc(
    const __nv_bfloat16* __restrict__ Qh, const __nv_bfloat16* __restrict__ Ql,
    const __nv_bfloat16* __restrict__ Kh, const __nv_bfloat16* __restrict__ Kl,
    const __nv_bfloat16* __restrict__ Vh, const __nv_bfloat16* __restrict__ Vl,
    float* __restrict__ Og)
{
    extern __shared__ __nv_bfloat16 asm_s[];
    const int tid = threadIdx.x, warp = tid >> 5, lane = tid & 31;
    const int g = lane >> 2, tg = lane & 3;
    const int h = blockIdx.y, b = blockIdx.z;
    const int q0 = blockIdx.x * AQ;
    const size_t tokbase = (size_t)b * T_SEQ;
    const uint32_t sbase = smem_u32(asm_s);
    const int NT = T_SEQ / AK;

    const int lrow16 = (lane & 7) + ((lane & 16) ? 8 : 0);
    const uint32_t kLane = (uint32_t)(lrow16 * KSTR + ((lane & 8) ? 8 : 0)) * 2u;
    const uint32_t vLane = (uint32_t)((lane & 15) * KSTR + ((lane & 16) ? 8 : 0)) * 2u
                         + (uint32_t)V_BASE * 2u;

    const int qr = q0 + warp * 16;
    uint32_t qfh[8][4], qfl[8][4];
    {
        const __nv_bfloat16* bh_ = Qh + (tokbase + qr) * D_MODEL + h * D_HEAD;
        const __nv_bfloat16* bl_ = Ql + (tokbase + qr) * D_MODEL + h * D_HEAD;
#pragma unroll
        for (int ks = 0; ks < 8; ks++) {
            int k0 = ks * 16 + 2 * tg;
            qfh[ks][0] = *(const uint32_t*)(bh_ + (size_t)g * D_MODEL + k0);
            qfh[ks][1] = *(const uint32_t*)(bh_ + (size_t)(g + 8) * D_MODEL + k0);
            qfh[ks][2] = *(const uint32_t*)(bh_ + (size_t)g * D_MODEL + k0 + 8);
            qfh[ks][3] = *(const uint32_t*)(bh_ + (size_t)(g + 8) * D_MODEL + k0 + 8);
            qfl[ks][0] = *(const uint32_t*)(bl_ + (size_t)g * D_MODEL + k0);
            qfl[ks][1] = *(const uint32_t*)(bl_ + (size_t)(g + 8) * D_MODEL + k0);
            qfl[ks][2] = *(const uint32_t*)(bl_ + (size_t)g * D_MODEL + k0 + 8);
            qfl[ks][3] = *(const uint32_t*)(bl_ + (size_t)(g + 8) * D_MODEL + k0 + 8);
        }
    }

    float Oacc[16][4];
#pragma unroll
    for (int d = 0; d < 16; d++)
#pragma unroll
        for (int r = 0; r < 4; r++) Oacc[d][r] = 0.f;
    float mA = -1e30f, mB = -1e30f, lA = 0.f, lB = 0.f;

#define LOAD_K(kt, s) do {                                                           \
        uint32_t _sb = sbase + (uint32_t)((s) * KSTAGE) * 2u;                        \
        _Pragma("unroll")                                                            \
        for (int _i = 0; _i < 16; _i++) {                                            \
            int _c = tid + _i * 128;                                                 \
            int _m = _c & 1023; int _row = _m >> 4, _j = _m & 15;                    \
            const __nv_bfloat16* _bp = (_c < 1024) ? Kh : Kl;                        \
            const __nv_bfloat16* _src = _bp + (tokbase + (size_t)(kt) * AK + _row)   \
                                        * D_MODEL + h * D_HEAD + _j * 8;             \
            uint32_t _dst = _sb + (uint32_t)(((_c < 1024) ? 0 : K_ELEMS)             \
                            + _row * KSTR + _j * 8) * 2u;                            \
            asm volatile("cp.async.cg.shared.global [%0], [%1], 16;"                 \
                         :: "r"(_dst), "l"(_src));                                   \
        } } while (0)

#define LOAD_V(kt) do {                                                              \
        uint32_t _sb = sbase + (uint32_t)V_BASE * 2u;                                \
        _Pragma("unroll")                                                            \
        for (int _i = 0; _i < 16; _i++) {                                            \
            int _c = tid + _i * 128;                                                 \
            int _m = _c & 1023; int _row = _m >> 4, _j = _m & 15;                    \
            const __nv_bfloat16* _bp = (_c < 1024) ? Vh : Vl;                        \
            const __nv_bfloat16* _src = _bp + (tokbase + (size_t)(kt) * AK + _row)   \
                                        * D_MODEL + h * D_HEAD + _j * 8;             \
            uint32_t _dst = _sb + (uint32_t)(((_c < 1024) ? 0 : K_ELEMS)             \
                            + _row * KSTR + _j * 8) * 2u;                            \
            asm volatile("cp.async.cg.shared.global [%0], [%1], 16;"                 \
                         :: "r"(_dst), "l"(_src));                                   \
        } } while (0)

    LOAD_K(0, 0);
    asm volatile("cp.async.commit_group;" ::: "memory");

    for (int kt = 0; kt < NT; kt++) {
        __syncthreads();
        LOAD_V(kt);
        asm volatile("cp.async.commit_group;" ::: "memory");
        if (kt + 1 < NT) LOAD_K(kt + 1, (kt + 1) & 1);
        asm volatile("cp.async.commit_group;" ::: "memory");
        asm volatile("cp.async.wait_group 2;" ::: "memory");
        __syncthreads();

        const uint32_t kB = sbase + (uint32_t)((kt & 1) * KSTAGE) * 2u + kLane;

        float sf[8][4];
#pragma unroll
        for (int p = 0; p < 4; p++) {
            float acc0[4] = {0.f, 0.f, 0.f, 0.f};
            float acc1[4] = {0.f, 0.f, 0.f, 0.f};
#pragma unroll
            for (int ks = 0; ks < 8; ks++) {
                uint32_t ad = kB + (uint32_t)(p * 16 * KSTR + ks * 16) * 2u;
                uint32_t kh[4], kl[4];
                LDSM4(kh, ad);
                LDSM4(kl, ad + (uint32_t)K_ELEMS * 2u);
                mma_bf16(acc0, qfh[ks][0], qfh[ks][1], qfh[ks][2], qfh[ks][3], kl[0], kl[1]);
                mma_bf16(acc0, qfl[ks][0], qfl[ks][1], qfl[ks][2], qfl[ks][3], kh[0], kh[1]);
                mma_bf16(acc0, qfh[ks][0], qfh[ks][1], qfh[ks][2], qfh[ks][3], kh[0], kh[1]);
                mma_bf16(acc1, qfh[ks][0], qfh[ks][1], qfh[ks][2], qfh[ks][3], kl[2], kl[3]);
                mma_bf16(acc1, qfl[ks][0], qfl[ks][1], qfl[ks][2], qfl[ks][3], kh[2], kh[3]);
                mma_bf16(acc1, qfh[ks][0], qfh[ks][1], qfh[ks][2], qfh[ks][3], kh[2], kh[3]);
            }
#pragma unroll
            for (int r = 0; r < 4; r++) {
                sf[2 * p][r] = acc0[r];
                sf[2 * p + 1][r] = acc1[r];
            }
        }

        float tmA = fmaxf(sf[0][0], sf[0][1]);
        float tmB = fmaxf(sf[0][2], sf[0][3]);
#pragma unroll
        for (int n = 1; n < 8; n++) {
            tmA = fmaxf(tmA, fmaxf(sf[n][0], sf[n][1]));
            tmB = fmaxf(tmB, fmaxf(sf[n][2], sf[n][3]));
        }
        tmA = fmaxf(tmA, __shfl_xor_sync(0xffffffffu, tmA, 1));
        tmA = fmaxf(tmA, __shfl_xor_sync(0xffffffffu, tmA, 2));
        tmB = fmaxf(tmB, __shfl_xor_sync(0xffffffffu, tmB, 1));
        tmB = fmaxf(tmB, __shfl_xor_sync(0xffffffffu, tmB, 2));
        float mAn = fmaxf(mA, tmA), mBn = fmaxf(mB, tmB);
        float corrA = ex2f(mA - mAn), corrB = ex2f(mB - mBn);
        mA = mAn; mB = mBn;

        float sumA = 0.f, sumB = 0.f;
#pragma unroll
        for (int n = 0; n < 8; n++) {
            sf[n][0] = ex2f(sf[n][0] - mA);
            sf[n][1] = ex2f(sf[n][1] - mA);
            sf[n][2] = ex2f(sf[n][2] - mB);
            sf[n][3] = ex2f(sf[n][3] - mB);
            sumA += sf[n][0] + sf[n][1];
            sumB += sf[n][2] + sf[n][3];
        }
        sumA += __shfl_xor_sync(0xffffffffu, sumA, 1);
        sumA += __shfl_xor_sync(0xffffffffu, sumA, 2);
        sumB += __shfl_xor_sync(0xffffffffu, sumB, 1);
        sumB += __shfl_xor_sync(0xffffffffu, sumB, 2);
        lA = lA * corrA + sumA;
        lB = lB * corrB + sumB;

#pragma unroll
        for (int d = 0; d < 16; d++) {
            Oacc[d][0] *= corrA; Oacc[d][1] *= corrA;
            Oacc[d][2] *= corrB; Oacc[d][3] *= corrB;
        }

        uint32_t pfh[4][4], pfl[4][4];
#pragma unroll
        for (int kv = 0; kv < 4; kv++) {
#pragma unroll
            for (int half = 0; half < 2; half++) {
                int n = 2 * kv + half;
                float p0 = sf[n][0], p1 = sf[n][1], p2 = sf[n][2], p3 = sf[n][3];
                __nv_bfloat162 h01 = __floats2bfloat162_rn(p0, p1);
                __nv_bfloat162 h23 = __floats2bfloat162_rn(p2, p3);
                __nv_bfloat162 l01 = __floats2bfloat162_rn(
                    p0 - __bfloat162float(h01.x), p1 - __bfloat162float(h01.y));
                __nv_bfloat162 l23 = __floats2bfloat162_rn(
                    p2 - __bfloat162float(h23.x), p3 - __bfloat162float(h23.y));
                pfh[kv][0 + 2 * half] = *(uint32_t*)&h01;
                pfh[kv][1 + 2 * half] = *(uint32_t*)&h23;
                pfl[kv][0 + 2 * half] = *(uint32_t*)&l01;
                pfl[kv][1 + 2 * half] = *(uint32_t*)&l23;
            }
        }

        asm volatile("cp.async.wait_group 1;" ::: "memory");
        __syncthreads();

#pragma unroll
        for (int dp = 0; dp < 8; dp++) {
#pragma unroll
            for (int kv = 0; kv < 4; kv++) {
                uint32_t vbase = sbase + vLane
                               + (uint32_t)(kv * 16 * KSTR + dp * 16) * 2u;
                uint32_t vh[4], vl[4];
                LDSM4T(vh, vbase);
                LDSM4T(vl, vbase + (uint32_t)K_ELEMS * 2u);
                float* oc0 = Oacc[2 * dp];
                float* oc1 = Oacc[2 * dp + 1];
                mma_bf16(oc0, pfh[kv][0], pfh[kv][1], pfh[kv][2], pfh[kv][3], vl[0], vl[1]);
                mma_bf16(oc0, pfl[kv][0], pfl[kv][1], pfl[kv][2], pfl[kv][3], vh[0], vh[1]);
                mma_bf16(oc0, pfh[kv][0], pfh[kv][1], pfh[kv][2], pfh[kv][3], vh[0], vh[1]);
                mma_bf16(oc1, pfh[kv][0], pfh[kv][1], pfh[kv][2], pfh[kv][3], vl[2], vl[3]);
                mma_bf16(oc1, pfl[kv][0], pfl[kv][1], pfl[kv][2], pfl[kv][3], vh[2], vh[3]);
                mma_bf16(oc1, pfh[kv][0], pfh[kv][1], pfh[kv][2], pfh[kv][3], vh[2], vh[3]);
            }
        }
    }

    float liA = 1.0f / lA, liB = 1.0f / lB;
    const size_t rowA = (tokbase + qr + g) * D_MODEL + h * D_HEAD;
    const size_t rowB = (tokbase + qr + g + 8) * D_MODEL + h * D_HEAD;
#pragma unroll
    for (int d = 0; d < 16; d++) {
        *(float2*)(Og + rowA + d * 8 + 2 * tg) =
            make_float2(Oacc[d][0] * liA, Oacc[d][1] * liA);
        *(float2*)(Og + rowB + d * 8 + 2 * tg) =
            make_float2(Oacc[d][2] * liB, Oacc[d][3] * liB);
    }
#undef LOAD_K
#undef LOAD_V
}

// ---------------- host launch ----------------
extern "C" void kernel_launch(void* const* d_in, const int* in_sizes, int n_in,
                              void* d_out, int out_size)
{
    const float* x   = (const float*)d_in[0];
    const float* cosb= (const float*)d_in[1];
    const float* sinb= (const float*)d_in[2];
    const float* Wq  = (const float*)d_in[3];
    const float* bq  = (const float*)d_in[4];
    const float* Wk  = (const float*)d_in[5];
    const float* bk  = (const float*)d_in[6];
    const float* Wv  = (const float*)d_in[7];
    const float* bv  = (const float*)d_in[8];
    const float* qnw = (const float*)d_in[9];
    const float* knw = (const float*)d_in[10];
    const float* Wo  = (const float*)d_in[11];
    const float* bo  = (const float*)d_in[12];
    float* out = (float*)d_out;

    const int BT = in_sizes[0] / D_MODEL;    // 4096
    const int Bb = BT / T_SEQ;               // 2

    float *qp, *kp, *ap;
    cudaGetSymbolAddress((void**)&qp, g_q);
    cudaGetSymbolAddress((void**)&kp, g_k);
    cudaGetSymbolAddress((void**)&ap, g_attn);
    __nv_bfloat16 *qh, *ql, *kh, *kl, *vh, *vl;
    cudaGetSymbolAddress((void**)&qh, g_qh);
    cudaGetSymbolAddress((void**)&ql, g_ql);
    cudaGetSymbolAddress((void**)&kh, g_kh);
    cudaGetSymbolAddress((void**)&kl, g_kl);
    cudaGetSymbolAddress((void**)&vh, g_vh);
    cudaGetSymbolAddress((void**)&vl, g_vl);
    int8_t *xq0, *xq1, *wq0, *wq1, *aq0, *aq1;
    float *xs, *ws, *as;
    cudaGetSymbolAddress((void**)&xq0, g_xq0);
    cudaGetSymbolAddress((void**)&xq1, g_xq1);
    cudaGetSymbolAddress((void**)&wq0, g_wq0);
    cudaGetSymbolAddress((void**)&wq1, g_wq1);
    cudaGetSymbolAddress((void**)&aq0, g_aq0);
    cudaGetSymbolAddress((void**)&aq1, g_aq1);
    cudaGetSymbolAddress((void**)&xs, g_xs);
    cudaGetSymbolAddress((void**)&ws, g_ws);
    cudaGetSymbolAddress((void**)&as, g_as);

    cudaFuncSetAttribute(gemm_i8, cudaFuncAttributeMaxDynamicSharedMemorySize, I8_SMEM);
    cudaFuncSetAttribute(attn_tc, cudaFuncAttributeMaxDynamicSharedMemorySize, ATTN_SMEM);

    const size_t woff = (size_t)D_MODEL * D_MODEL;

    // quantize activations + weights
    quant_rows<<<BT, 256>>>(x, xq0, xq1, xs);
    dim3 wq(D_MODEL, 4);
    quant_w4<<<wq, 256>>>(Wq, Wk, Wv, Wo, wq0, wq1, ws);

    // fused QKV int8 GEMM: bz 0 -> Q fp32, 1 -> K fp32, 2 -> V bf16 hi/lo
    dim3 gq(D_MODEL / IN, BT / IM, 3);   // (16, 32, 3)
    gemm_i8<<<gq, 256, I8_SMEM>>>(xq0, xq1, xs, wq0, wq1, ws,
                                  bq, qp, bk, kp, bv, vh, vl,
                                  BT, D_MODEL, D_MODEL);

    const float qscale = 0.08838834764831845f * 1.4426950408889634f;
    dim3 rn(BT, 2);
    rmsnorm_rope_bf<<<rn, 256>>>(qp, kp, qnw, knw, cosb, sinb,
                                 qh, ql, kh, kl, qscale);

    dim3 adim(T_SEQ / AQ, N_HEADS, Bb);   // (32, 16, 2)
    attn_tc<<<adim, 128, ATTN_SMEM>>>(qh, ql, kh, kl, vh, vl, ap);

    // output projection
    quant_rows<<<BT, 256>>>(ap, aq0, aq1, as);
    dim3 go(D_MODEL / IN, BT / IM, 1);
    gemm_i8<<<go, 256, I8_SMEM>>>(aq0, aq1, as,
                                  wq0 + 3 * woff, wq1 + 3 * woff, ws + 3 * D_MODEL,
                                  bo, out, bo, out, bo,
                                  (__nv_bfloat16*)nullptr, (__nv_bfloat16*)nullptr,
                                  BT, D_MODEL, D_MODEL);
}

// round 15
// speedup vs baseline: 1.3344x; 1.3344x over previous
#include <cuda_runtime.h>
#include <cuda_bf16.h>
#include <cstdint>
#include <math.h>

#define D_MODEL 2048
#define T_SEQ   2048
#define N_HEADS 16
#define D_HEAD  128
#define BT_MAX  4096   // B=2 * T=2048

// ---------------- scratch (device globals; allocation-free) ----------------
__device__ float g_q[(size_t)BT_MAX * D_MODEL];
__device__ float g_k[(size_t)BT_MAX * D_MODEL];

__device__ __nv_bfloat16 g_xh[(size_t)BT_MAX * D_MODEL];
__device__ __nv_bfloat16 g_xl[(size_t)BT_MAX * D_MODEL];
__device__ __nv_bfloat16 g_wh[(size_t)4 * D_MODEL * D_MODEL];  // Wq,Wk,Wv,Wo hi
__device__ __nv_bfloat16 g_wl[(size_t)4 * D_MODEL * D_MODEL];  // lo
__device__ __nv_bfloat16 g_ah[(size_t)BT_MAX * D_MODEL];       // attn out hi
__device__ __nv_bfloat16 g_al[(size_t)BT_MAX * D_MODEL];

__device__ __nv_bfloat16 g_qh[(size_t)BT_MAX * D_MODEL];       // Q hi (scaled)
__device__ __nv_bfloat16 g_ql[(size_t)BT_MAX * D_MODEL];
__device__ __nv_bfloat16 g_kh[(size_t)BT_MAX * D_MODEL];       // K hi
__device__ __nv_bfloat16 g_kl[(size_t)BT_MAX * D_MODEL];
__device__ __nv_bfloat16 g_vh[(size_t)BT_MAX * D_MODEL];       // V hi [b*t, 2048]
__device__ __nv_bfloat16 g_vl[(size_t)BT_MAX * D_MODEL];

__device__ __forceinline__ uint32_t smem_u32(const void* p) {
    uint32_t a;
    asm("{ .reg .u64 t; cvta.to.shared.u64 t, %1; cvt.u32.u64 %0, t; }" : "=r"(a) : "l"(p));
    return a;
}

__device__ __forceinline__ void mma_bf16(float* c, uint32_t a0, uint32_t a1,
                                         uint32_t a2, uint32_t a3,
                                         uint32_t b0, uint32_t b1) {
    asm volatile(
        "mma.sync.aligned.m16n8k16.row.col.f32.bf16.bf16.f32 "
        "{%0,%1,%2,%3}, {%4,%5,%6,%7}, {%8,%9}, {%0,%1,%2,%3};"
        : "+f"(c[0]), "+f"(c[1]), "+f"(c[2]), "+f"(c[3])
        : "r"(a0), "r"(a1), "r"(a2), "r"(a3), "r"(b0), "r"(b1));
}

#define LDSM4(r, a) asm volatile(                                                  \
    "ldmatrix.sync.aligned.m8n8.x4.shared.b16 {%0,%1,%2,%3}, [%4];"                \
    : "=r"((r)[0]), "=r"((r)[1]), "=r"((r)[2]), "=r"((r)[3]) : "r"(a))

#define LDSM4T(r, a) asm volatile(                                                 \
    "ldmatrix.sync.aligned.m8n8.x4.trans.shared.b16 {%0,%1,%2,%3}, [%4];"          \
    : "=r"((r)[0]), "=r"((r)[1]), "=r"((r)[2]), "=r"((r)[3]) : "r"(a))

__device__ __forceinline__ float ex2f(float x) {
    float r;
    asm("ex2.approx.f32 %0, %1;" : "=f"(r) : "f"(x));
    return r;
}

// ---------------- split fp32 -> bf16 hi + bf16 lo ----------------
__global__ __launch_bounds__(256) void split_bf16(
    const float* __restrict__ src, __nv_bfloat16* __restrict__ hi,
    __nv_bfloat16* __restrict__ lo, int n4)
{
    int i = blockIdx.x * 256 + threadIdx.x;
    if (i >= n4) return;
    float4 v = ((const float4*)src)[i];
    __nv_bfloat16 h0 = __float2bfloat16(v.x);
    __nv_bfloat16 h1 = __float2bfloat16(v.y);
    __nv_bfloat16 h2 = __float2bfloat16(v.z);
    __nv_bfloat16 h3 = __float2bfloat16(v.w);
    __nv_bfloat16 l0 = __float2bfloat16(v.x - __bfloat162float(h0));
    __nv_bfloat16 l1 = __float2bfloat16(v.y - __bfloat162float(h1));
    __nv_bfloat16 l2 = __float2bfloat16(v.z - __bfloat162float(h2));
    __nv_bfloat16 l3 = __float2bfloat16(v.w - __bfloat162float(h3));
    __nv_bfloat162* hp = (__nv_bfloat162*)(hi + (size_t)i * 4);
    __nv_bfloat162* lp = (__nv_bfloat162*)(lo + (size_t)i * 4);
    hp[0] = __nv_bfloat162(h0, h1); hp[1] = __nv_bfloat162(h2, h3);
    lp[0] = __nv_bfloat162(l0, l1); lp[1] = __nv_bfloat162(l2, l3);
}

// merged weight split: blockIdx.y selects which W
__global__ __launch_bounds__(256) void split_bf16_w(
    const float* __restrict__ w0, const float* __restrict__ w1,
    const float* __restrict__ w2, const float* __restrict__ w3,
    __nv_bfloat16* __restrict__ hi, __nv_bfloat16* __restrict__ lo, int n4)
{
    int i = blockIdx.x * 256 + threadIdx.x;
    if (i >= n4) return;
    int y = blockIdx.y;
    const float* src = (y == 0) ? w0 : (y == 1) ? w1 : (y == 2) ? w2 : w3;
    size_t off = (size_t)y * n4;
    float4 v = ((const float4*)src)[i];
    __nv_bfloat16 h0 = __float2bfloat16(v.x);
    __nv_bfloat16 h1 = __float2bfloat16(v.y);
    __nv_bfloat16 h2 = __float2bfloat16(v.z);
    __nv_bfloat16 h3 = __float2bfloat16(v.w);
    __nv_bfloat16 l0 = __float2bfloat16(v.x - __bfloat162float(h0));
    __nv_bfloat16 l1 = __float2bfloat16(v.y - __bfloat162float(h1));
    __nv_bfloat16 l2 = __float2bfloat16(v.z - __bfloat162float(h2));
    __nv_bfloat16 l3 = __float2bfloat16(v.w - __bfloat162float(h3));
    __nv_bfloat162* hp = (__nv_bfloat162*)(hi + (off + i) * 4);
    __nv_bfloat162* lp = (__nv_bfloat162*)(lo + (off + i) * 4);
    hp[0] = __nv_bfloat162(h0, h1); hp[1] = __nv_bfloat162(h2, h3);
    lp[0] = __nv_bfloat162(l0, l1); lp[1] = __nv_bfloat162(l2, l3);
}

// ---------------- 3xBF16 GEMM, CTA 128x256, warp tile 64x64 ----------------
// bz==2 writes bf16 hi/lo (V path); otherwise fp32.
#define TM 128
#define TN 256
#define TKF 32
#define BSTR 40
#define A_REG (TM * BSTR)              // 5120
#define B_REG (TN * BSTR)              // 10240
#define STAGE_E (2 * A_REG + 2 * B_REG)  // 30720 elems
#define GSTAGES 3
#define GEMM_SMEM (GSTAGES * STAGE_E * 2)  // 184320 B

__global__ __launch_bounds__(256) void gemm_bf16(
    const __nv_bfloat16* __restrict__ Ah, const __nv_bfloat16* __restrict__ Al,
    const __nv_bfloat16* __restrict__ Wh, const __nv_bfloat16* __restrict__ Wl,
    const float* __restrict__ bias0, float* __restrict__ C0,
    const float* __restrict__ bias1, float* __restrict__ C1,
    const float* __restrict__ bias2,
    __nv_bfloat16* __restrict__ Vh, __nv_bfloat16* __restrict__ Vl,
    int M, int N, int K)
{
    extern __shared__ __nv_bfloat16 smem[];
    const int tid = threadIdx.x;
    const int bz = blockIdx.z;
    const __nv_bfloat16* Bh = Wh + (size_t)bz * D_MODEL * D_MODEL;
    const __nv_bfloat16* Bl = Wl + (size_t)bz * D_MODEL * D_MODEL;
    const float* bia = (bz == 0) ? bias0 : (bz == 1) ? bias1 : bias2;
    float*       C   = (bz == 0) ? C0 : C1;

    const int m0 = blockIdx.y * TM;
    const int n0 = blockIdx.x * TN;
    const int NTILES = K / TKF;   // 64

    const uint32_t sbase = smem_u32(smem);

    // ---- load mapping: 3072 16B-chunks per stage, 12 per thread ----
    const __nv_bfloat16* gsrc[12];
    uint32_t soff[12];
#pragma unroll
    for (int i = 0; i < 12; i++) {
        int c = tid + i * 256;
        if (c < 1024) {
            int m = c & 511, row = m >> 2, j = m & 3;
            const __nv_bfloat16* bp = (c < 512) ? Ah : Al;
            gsrc[i] = bp + (size_t)(m0 + row) * K + j * 8;
            soff[i] = (uint32_t)(((c < 512) ? 0 : A_REG) + row * BSTR + j * 8) * 2u;
        } else {
            int cb = c - 1024;
            int m = cb & 1023, row = m >> 2, j = m & 3;
            const __nv_bfloat16* bp = (cb < 1024) ? Bh : Bl;
            gsrc[i] = bp + (size_t)(n0 + row) * K + j * 8;
            soff[i] = (uint32_t)(2 * A_REG + ((cb < 1024) ? 0 : B_REG)
                     + row * BSTR + j * 8) * 2u;
        }
    }

#define LOAD_TILE(t, s) do {                                                     \
        uint32_t _sb = sbase + (uint32_t)((s) * STAGE_E) * 2u;                   \
        size_t _go = (size_t)(t) * TKF;                                          \
        _Pragma("unroll")                                                        \
        for (int _i = 0; _i < 12; _i++) {                                        \
            asm volatile("cp.async.cg.shared.global [%0], [%1], 16;"             \
                :: "r"(_sb + soff[_i]), "l"(gsrc[_i] + _go));                    \
        } } while (0)

    const int warp = tid >> 5, lane = tid & 31;
    const int wm = (warp >> 2) * 64, wn = (warp & 3) * 64;
    const int g = lane >> 2, tg = lane & 3;

    const uint32_t aLane = (uint32_t)((wm + (lane & 15)) * BSTR + (lane >> 4) * 8) * 2u;
    const int bnrow = wn + (lane & 7) + ((lane & 16) ? 8 : 0);
    const uint32_t bLane = (uint32_t)(2 * A_REG + bnrow * BSTR + ((lane & 8) ? 8 : 0)) * 2u;

    float c[4][8][4];
#pragma unroll
    for (int mi = 0; mi < 4; mi++)
#pragma unroll
        for (int ni = 0; ni < 8; ni++)
#pragma unroll
            for (int r = 0; r < 4; r++) c[mi][ni][r] = 0.f;

    LOAD_TILE(0, 0);
    asm volatile("cp.async.commit_group;" ::: "memory");
    LOAD_TILE(1, 1);
    asm volatile("cp.async.commit_group;" ::: "memory");

    for (int kt = 0; kt < NTILES; kt++) {
        asm volatile("cp.async.wait_group 1;" ::: "memory");
        __syncthreads();

        int lt = kt + 2;
        if (lt < NTILES) LOAD_TILE(lt, lt % GSTAGES);
        asm volatile("cp.async.commit_group;" ::: "memory");

        const uint32_t stb = sbase + (uint32_t)((kt % GSTAGES) * STAGE_E) * 2u;
        const uint32_t aB = stb + aLane;
        const uint32_t bB = stb + bLane;

#pragma unroll
        for (int ks = 0; ks < 2; ks++) {
            uint32_t ah[4][4], al[4][4];
#pragma unroll
            for (int mi = 0; mi < 4; mi++) {
                uint32_t ad = aB + (uint32_t)(mi * 16 * BSTR + ks * 16) * 2u;
                LDSM4(ah[mi], ad);
                LDSM4(al[mi], ad + (uint32_t)A_REG * 2u);
            }
#pragma unroll
            for (int p = 0; p < 4; p++) {
                uint32_t bd = bB + (uint32_t)(p * 16 * BSTR + ks * 16) * 2u;
                uint32_t bh[4], bl[4];
                LDSM4(bh, bd);
                LDSM4(bl, bd + (uint32_t)B_REG * 2u);
#pragma unroll
                for (int mi = 0; mi < 4; mi++) {
#pragma unroll
                    for (int hf = 0; hf < 2; hf++) {
                        float* cc = c[mi][2 * p + hf];
                        mma_bf16(cc, ah[mi][0], ah[mi][1], ah[mi][2], ah[mi][3],
                                 bl[2 * hf], bl[2 * hf + 1]);
                        mma_bf16(cc, al[mi][0], al[mi][1], al[mi][2], al[mi][3],
                                 bh[2 * hf], bh[2 * hf + 1]);
                        mma_bf16(cc, ah[mi][0], ah[mi][1], ah[mi][2], ah[mi][3],
                                 bh[2 * hf], bh[2 * hf + 1]);
                    }
                }
            }
        }
    }

    // ---- epilogue ----
#pragma unroll
    for (int ni = 0; ni < 8; ni++) {
        int col = n0 + wn + ni * 8 + 2 * tg;
        float2 bb = *(const float2*)(bia + col);
#pragma unroll
        for (int mi = 0; mi < 4; mi++) {
            int row = m0 + wm + mi * 16 + g;
            float o00 = c[mi][ni][0] + bb.x, o01 = c[mi][ni][1] + bb.y;
            float o10 = c[mi][ni][2] + bb.x, o11 = c[mi][ni][3] + bb.y;
            if (bz == 2) {
                __nv_bfloat162 h0 = __floats2bfloat162_rn(o00, o01);
                __nv_bfloat162 l0 = __floats2bfloat162_rn(
                    o00 - __bfloat162float(h0.x), o01 - __bfloat162float(h0.y));
                __nv_bfloat162 h1 = __floats2bfloat162_rn(o10, o11);
                __nv_bfloat162 l1 = __floats2bfloat162_rn(
                    o10 - __bfloat162float(h1.x), o11 - __bfloat162float(h1.y));
                *(__nv_bfloat162*)(Vh + (size_t)row * N + col) = h0;
                *(__nv_bfloat162*)(Vl + (size_t)row * N + col) = l0;
                *(__nv_bfloat162*)(Vh + (size_t)(row + 8) * N + col) = h1;
                *(__nv_bfloat162*)(Vl + (size_t)(row + 8) * N + col) = l1;
            } else {
                float2 w0 = make_float2(o00, o01), w1 = make_float2(o10, o11);
                *(float2*)(C + (size_t)row * N + col) = w0;
                *(float2*)(C + (size_t)(row + 8) * N + col) = w1;
            }
        }
    }
#undef LOAD_TILE
}

// ---------------- fused RMSNorm + RoPE -> bf16 hi/lo; blockIdx.y: 0=Q, 1=K ----------------
__global__ __launch_bounds__(256) void rmsnorm_rope_bf(
    const float* __restrict__ qsrc, const float* __restrict__ ksrc,
    const float* __restrict__ qw, const float* __restrict__ kw,
    const float* __restrict__ cosb, const float* __restrict__ sinb,
    __nv_bfloat16* __restrict__ qoh, __nv_bfloat16* __restrict__ qol,
    __nv_bfloat16* __restrict__ koh, __nv_bfloat16* __restrict__ kol,
    float qscale)
{
    const int which = blockIdx.y;
    const float* hsrc = which ? ksrc : qsrc;
    const float* w    = which ? kw   : qw;
    __nv_bfloat16* oh = which ? koh  : qoh;
    __nv_bfloat16* ol = which ? kol  : qol;
    const float outscale = which ? 1.0f : qscale;

    const int row = blockIdx.x;
    const int t = row & (T_SEQ - 1);
    const float* hp = hsrc + (size_t)row * D_MODEL;
    const float* cp = cosb + (size_t)t * D_MODEL;
    const float* sp = sinb + (size_t)t * D_MODEL;
    const int tid = threadIdx.x;

    float4 vals[2];
    float ss = 0.f;
#pragma unroll
    for (int i = 0; i < 2; i++) {
        float4 v = ((const float4*)hp)[tid + i * 256];
        vals[i] = v;
        ss += v.x * v.x + v.y * v.y + v.z * v.z + v.w * v.w;
    }
#pragma unroll
    for (int o = 16; o > 0; o >>= 1) ss += __shfl_xor_sync(0xffffffffu, ss, o);
    __shared__ float red[8];
    __shared__ float s_inv;
    if ((tid & 31) == 0) red[tid >> 5] = ss;
    __syncthreads();
    if (tid == 0) {
        float tot = 0.f;
#pragma unroll
        for (int i = 0; i < 8; i++) tot += red[i];
        s_inv = rsqrtf(tot * (1.0f / D_MODEL) + 1e-6f);
    }
    __syncthreads();
    const float inv = s_inv;

#pragma unroll
    for (int i = 0; i < 2; i++) {
        int fi = tid + i * 256;
        float4 v = vals[i];
        float4 wv = ((const float4*)w)[fi];
        float4 c4 = ((const float4*)cp)[fi];
        float4 s4 = ((const float4*)sp)[fi];
        float nx = v.x * inv * wv.x;
        float ny = v.y * inv * wv.y;
        float nz = v.z * inv * wv.z;
        float nw = v.w * inv * wv.w;
        float o0 = (nx * c4.x - ny * s4.x) * outscale;
        float o1 = (ny * c4.y + nx * s4.y) * outscale;
        float o2 = (nz * c4.z - nw * s4.z) * outscale;
        float o3 = (nw * c4.w + nz * s4.w) * outscale;
        __nv_bfloat16 h0 = __float2bfloat16(o0), h1 = __float2bfloat16(o1);
        __nv_bfloat16 h2 = __float2bfloat16(o2), h3 = __float2bfloat16(o3);
        __nv_bfloat16 l0 = __float2bfloat16(o0 - __bfloat162float(h0));
        __nv_bfloat16 l1 = __float2bfloat16(o1 - __bfloat162float(h1));
        __nv_bfloat16 l2 = __float2bfloat16(o2 - __bfloat162float(h2));
        __nv_bfloat16 l3 = __float2bfloat16(o3 - __bfloat162float(h3));
        __nv_bfloat162* hp2 = (__nv_bfloat162*)(oh + (size_t)row * D_MODEL + fi * 4);
        __nv_bfloat162* lp2 = (__nv_bfloat162*)(ol + (size_t)row * D_MODEL + fi * 4);
        hp2[0] = __nv_bfloat162(h0, h1); hp2[1] = __nv_bfloat162(h2, h3);
        lp2[0] = __nv_bfloat162(l0, l1); lp2[1] = __nv_bfloat162(l2, l3);
    }
}

// ---------------- tensor-core flash attention (3xBF16, 2 CTAs/SM) ----------------
// AQ=64, 128 threads. K double-buffered, V single-buffered. V trans via ldmatrix.
#define AQ 64
#define AK 64
#define KSTR 136
#define K_ELEMS (AK * KSTR)                  // 8704
#define KSTAGE (2 * K_ELEMS)                 // hi+lo, 17408 elems
#define V_BASE (2 * KSTAGE)                  // after 2 K stages
#define ATTN_ELEMS (V_BASE + 2 * K_ELEMS)    // 52224 elems
#define ATTN_SMEM (ATTN_ELEMS * 2)           // 104448 B

__global__ __launch_bounds__(128, 2) void attn_tc(
    const __nv_bfloat16* __restrict__ Qh, const __nv_bfloat16* __restrict__ Ql,
    const __nv_bfloat16* __restrict__ Kh, const __nv_bfloat16* __restrict__ Kl,
    const __nv_bfloat16* __restrict__ Vh, const __nv_bfloat16* __restrict__ Vl,
    __nv_bfloat16* __restrict__ Oh, __nv_bfloat16* __restrict__ Ol)
{
    extern __shared__ __nv_bfloat16 asm_s[];
    const int tid = threadIdx.x, warp = tid >> 5, lane = tid & 31;
    const int g = lane >> 2, tg = lane & 3;
    const int h = blockIdx.y, b = blockIdx.z;
    const int q0 = blockIdx.x * AQ;
    const size_t tokbase = (size_t)b * T_SEQ;
    const uint32_t sbase = smem_u32(asm_s);
    const int NT = T_SEQ / AK;   // 32

    // K fragment lane base (non-trans): rows = token
    const int lrow16 = (lane & 7) + ((lane & 16) ? 8 : 0);
    const uint32_t kLane = (uint32_t)(lrow16 * KSTR + ((lane & 8) ? 8 : 0)) * 2u;
    // V fragment lane base (trans): rows = token (lane&15), col half by lane&16
    const uint32_t vLane = (uint32_t)((lane & 15) * KSTR + ((lane & 16) ? 8 : 0)) * 2u
                         + (uint32_t)V_BASE * 2u;

    // ---- Q fragments in registers (16 rows per warp) ----
    const int qr = q0 + warp * 16;
    uint32_t qfh[8][4], qfl[8][4];
    {
        const __nv_bfloat16* bh_ = Qh + (tokbase + qr) * D_MODEL + h * D_HEAD;
        const __nv_bfloat16* bl_ = Ql + (tokbase + qr) * D_MODEL + h * D_HEAD;
#pragma unroll
        for (int ks = 0; ks < 8; ks++) {
            int k0 = ks * 16 + 2 * tg;
            qfh[ks][0] = *(const uint32_t*)(bh_ + (size_t)g * D_MODEL + k0);
            qfh[ks][1] = *(const uint32_t*)(bh_ + (size_t)(g + 8) * D_MODEL + k0);
            qfh[ks][2] = *(const uint32_t*)(bh_ + (size_t)g * D_MODEL + k0 + 8);
            qfh[ks][3] = *(const uint32_t*)(bh_ + (size_t)(g + 8) * D_MODEL + k0 + 8);
            qfl[ks][0] = *(const uint32_t*)(bl_ + (size_t)g * D_MODEL + k0);
            qfl[ks][1] = *(const uint32_t*)(bl_ + (size_t)(g + 8) * D_MODEL + k0);
            qfl[ks][2] = *(const uint32_t*)(bl_ + (size_t)g * D_MODEL + k0 + 8);
            qfl[ks][3] = *(const uint32_t*)(bl_ + (size_t)(g + 8) * D_MODEL + k0 + 8);
        }
    }

    float Oacc[16][4];
#pragma unroll
    for (int d = 0; d < 16; d++)
#pragma unroll
        for (int r = 0; r < 4; r++) Oacc[d][r] = 0.f;
    float mA = -1e30f, mB = -1e30f, lA = 0.f, lB = 0.f;

    // 2048 chunks per K/V load, 16 per thread (128 threads)
#define LOAD_K(kt, s) do {                                                           \
        uint32_t _sb = sbase + (uint32_t)((s) * KSTAGE) * 2u;                        \
        _Pragma("unroll")                                                            \
        for (int _i = 0; _i < 16; _i++) {                                            \
            int _c = tid + _i * 128;                                                 \
            int _m = _c & 1023; int _row = _m >> 4, _j = _m & 15;                    \
            const __nv_bfloat16* _bp = (_c < 1024) ? Kh : Kl;                        \
            const __nv_bfloat16* _src = _bp + (tokbase + (size_t)(kt) * AK + _row)   \
                                        * D_MODEL + h * D_HEAD + _j * 8;             \
            uint32_t _dst = _sb + (uint32_t)(((_c < 1024) ? 0 : K_ELEMS)             \
                            + _row * KSTR + _j * 8) * 2u;                            \
            asm volatile("cp.async.cg.shared.global [%0], [%1], 16;"                 \
                         :: "r"(_dst), "l"(_src));                                   \
        } } while (0)

#define LOAD_V(kt) do {                                                              \
        uint32_t _sb = sbase + (uint32_t)V_BASE * 2u;                                \
        _Pragma("unroll")                                                            \
        for (int _i = 0; _i < 16; _i++) {                                            \
            int _c = tid + _i * 128;                                                 \
            int _m = _c & 1023; int _row = _m >> 4, _j = _m & 15;                    \
            const __nv_bfloat16* _bp = (_c < 1024) ? Vh : Vl;                        \
            const __nv_bfloat16* _src = _bp + (tokbase + (size_t)(kt) * AK + _row)   \
                                        * D_MODEL + h * D_HEAD + _j * 8;             \
            uint32_t _dst = _sb + (uint32_t)(((_c < 1024) ? 0 : K_ELEMS)             \
                            + _row * KSTR + _j * 8) * 2u;                            \
            asm volatile("cp.async.cg.shared.global [%0], [%1], 16;"                 \
                         :: "r"(_dst), "l"(_src));                                   \
        } } while (0)

    LOAD_K(0, 0);
    asm volatile("cp.async.commit_group;" ::: "memory");

    for (int kt = 0; kt < NT; kt++) {
        __syncthreads();   // all warps done with V buffer + K stage (kt+1)&1
        LOAD_V(kt);
        asm volatile("cp.async.commit_group;" ::: "memory");
        if (kt + 1 < NT) LOAD_K(kt + 1, (kt + 1) & 1);
        asm volatile("cp.async.commit_group;" ::: "memory");   // always (maybe empty)
        asm volatile("cp.async.wait_group 2;" ::: "memory");   // K(kt) ready
        __syncthreads();

        const uint32_t kB = sbase + (uint32_t)((kt & 1) * KSTAGE) * 2u + kLane;

        // ---- S = Q K^T (16 x 64 per warp) ----
        float sf[8][4];
#pragma unroll
        for (int p = 0; p < 4; p++) {
            float acc0[4] = {0.f, 0.f, 0.f, 0.f};
            float acc1[4] = {0.f, 0.f, 0.f, 0.f};
#pragma unroll
            for (int ks = 0; ks < 8; ks++) {
                uint32_t ad = kB + (uint32_t)(p * 16 * KSTR + ks * 16) * 2u;
                uint32_t kh[4], kl[4];
                LDSM4(kh, ad);
                LDSM4(kl, ad + (uint32_t)K_ELEMS * 2u);
                mma_bf16(acc0, qfh[ks][0], qfh[ks][1], qfh[ks][2], qfh[ks][3], kl[0], kl[1]);
                mma_bf16(acc0, qfl[ks][0], qfl[ks][1], qfl[ks][2], qfl[ks][3], kh[0], kh[1]);
                mma_bf16(acc0, qfh[ks][0], qfh[ks][1], qfh[ks][2], qfh[ks][3], kh[0], kh[1]);
                mma_bf16(acc1, qfh[ks][0], qfh[ks][1], qfh[ks][2], qfh[ks][3], kl[2], kl[3]);
                mma_bf16(acc1, qfl[ks][0], qfl[ks][1], qfl[ks][2], qfl[ks][3], kh[2], kh[3]);
                mma_bf16(acc1, qfh[ks][0], qfh[ks][1], qfh[ks][2], qfh[ks][3], kh[2], kh[3]);
            }
#pragma unroll
            for (int r = 0; r < 4; r++) {
                sf[2 * p][r] = acc0[r];
                sf[2 * p + 1][r] = acc1[r];
            }
        }

        // ---- online softmax (exp2 domain; Q pre-scaled by scale*log2e) ----
        float tmA = fmaxf(sf[0][0], sf[0][1]);
        float tmB = fmaxf(sf[0][2], sf[0][3]);
#pragma unroll
        for (int n = 1; n < 8; n++) {
            tmA = fmaxf(tmA, fmaxf(sf[n][0], sf[n][1]));
            tmB = fmaxf(tmB, fmaxf(sf[n][2], sf[n][3]));
        }
        tmA = fmaxf(tmA, __shfl_xor_sync(0xffffffffu, tmA, 1));
        tmA = fmaxf(tmA, __shfl_xor_sync(0xffffffffu, tmA, 2));
        tmB = fmaxf(tmB, __shfl_xor_sync(0xffffffffu, tmB, 1));
        tmB = fmaxf(tmB, __shfl_xor_sync(0xffffffffu, tmB, 2));
        float mAn = fmaxf(mA, tmA), mBn = fmaxf(mB, tmB);
        float corrA = ex2f(mA - mAn), corrB = ex2f(mB - mBn);
        mA = mAn; mB = mBn;

        float sumA = 0.f, sumB = 0.f;
#pragma unroll
        for (int n = 0; n < 8; n++) {
            sf[n][0] = ex2f(sf[n][0] - mA);
            sf[n][1] = ex2f(sf[n][1] - mA);
            sf[n][2] = ex2f(sf[n][2] - mB);
            sf[n][3] = ex2f(sf[n][3] - mB);
            sumA += sf[n][0] + sf[n][1];
            sumB += sf[n][2] + sf[n][3];
        }
        sumA += __shfl_xor_sync(0xffffffffu, sumA, 1);
        sumA += __shfl_xor_sync(0xffffffffu, sumA, 2);
        sumB += __shfl_xor_sync(0xffffffffu, sumB, 1);
        sumB += __shfl_xor_sync(0xffffffffu, sumB, 2);
        lA = lA * corrA + sumA;
        lB = lB * corrB + sumB;

#pragma unroll
        for (int d = 0; d < 16; d++) {
            Oacc[d][0] *= corrA; Oacc[d][1] *= corrA;
            Oacc[d][2] *= corrB; Oacc[d][3] *= corrB;
        }

        // ---- P fragments (hi/lo bf16) ----
        uint32_t pfh[4][4], pfl[4][4];
#pragma unroll
        for (int kv = 0; kv < 4; kv++) {
#pragma unroll
            for (int half = 0; half < 2; half++) {
                int n = 2 * kv + half;
                float p0 = sf[n][0], p1 = sf[n][1], p2 = sf[n][2], p3 = sf[n][3];
                __nv_bfloat162 h01 = __floats2bfloat162_rn(p0, p1);
                __nv_bfloat162 h23 = __floats2bfloat162_rn(p2, p3);
                __nv_bfloat162 l01 = __floats2bfloat162_rn(
                    p0 - __bfloat162float(h01.x), p1 - __bfloat162float(h01.y));
                __nv_bfloat162 l23 = __floats2bfloat162_rn(
                    p2 - __bfloat162float(h23.x), p3 - __bfloat162float(h23.y));
                pfh[kv][0 + 2 * half] = *(uint32_t*)&h01;
                pfh[kv][1 + 2 * half] = *(uint32_t*)&h23;
                pfl[kv][0 + 2 * half] = *(uint32_t*)&l01;
                pfl[kv][1 + 2 * half] = *(uint32_t*)&l23;
            }
        }

        // ---- wait for V, then O += P V (trans ldmatrix) ----
        asm volatile("cp.async.wait_group 1;" ::: "memory");   // V(kt) ready
        __syncthreads();

#pragma unroll
        for (int dp = 0; dp < 8; dp++) {
#pragma unroll
            for (int kv = 0; kv < 4; kv++) {
                uint32_t vbase = sbase + vLane
                               + (uint32_t)(kv * 16 * KSTR + dp * 16) * 2u;
                uint32_t vh[4], vl[4];
                LDSM4T(vh, vbase);
                LDSM4T(vl, vbase + (uint32_t)K_ELEMS * 2u);
                float* oc0 = Oacc[2 * dp];
                float* oc1 = Oacc[2 * dp + 1];
                mma_bf16(oc0, pfh[kv][0], pfh[kv][1], pfh[kv][2], pfh[kv][3], vl[0], vl[1]);
                mma_bf16(oc0, pfl[kv][0], pfl[kv][1], pfl[kv][2], pfl[kv][3], vh[0], vh[1]);
                mma_bf16(oc0, pfh[kv][0], pfh[kv][1], pfh[kv][2], pfh[kv][3], vh[0], vh[1]);
                mma_bf16(oc1, pfh[kv][0], pfh[kv][1], pfh[kv][2], pfh[kv][3], vl[2], vl[3]);
                mma_bf16(oc1, pfl[kv][0], pfl[kv][1], pfl[kv][2], pfl[kv][3], vh[2], vh[3]);
                mma_bf16(oc1, pfh[kv][0], pfh[kv][1], pfh[kv][2], pfh[kv][3], vh[2], vh[3]);
            }
        }
    }

    // ---- finalize: write bf16 hi/lo ----
    float liA = 1.0f / lA, liB = 1.0f / lB;
    const size_t rowA = (tokbase + qr + g) * D_MODEL + h * D_HEAD;
    const size_t rowB = (tokbase + qr + g + 8) * D_MODEL + h * D_HEAD;
#pragma unroll
    for (int d = 0; d < 16; d++) {
        float a0 = Oacc[d][0] * liA, a1 = Oacc[d][1] * liA;
        float b0 = Oacc[d][2] * liB, b1 = Oacc[d][3] * liB;
        __nv_bfloat162 hA = __floats2bfloat162_rn(a0, a1);
        __nv_bfloat162 lAv = __floats2bfloat162_rn(a0 - __bfloat162float(hA.x),
                                                   a1 - __bfloat162float(hA.y));
        __nv_bfloat162 hB = __floats2bfloat162_rn(b0, b1);
        __nv_bfloat162 lBv = __floats2bfloat162_rn(b0 - __bfloat162float(hB.x),
                                                   b1 - __bfloat162float(hB.y));
        *(__nv_bfloat162*)(Oh + rowA + d * 8 + 2 * tg) = hA;
        *(__nv_bfloat162*)(Ol + rowA + d * 8 + 2 * tg) = lAv;
        *(__nv_bfloat162*)(Oh + rowB + d * 8 + 2 * tg) = hB;
        *(__nv_bfloat162*)(Ol + rowB + d * 8 + 2 * tg) = lBv;
    }
#undef LOAD_K
#undef LOAD_V
}

// ---------------- host launch ----------------
extern "C" void kernel_launch(void* const* d_in, const int* in_sizes, int n_in,
                              void* d_out, int out_size)
{
    const float* x   = (const float*)d_in[0];
    const float* cosb= (const float*)d_in[1];
    const float* sinb= (const float*)d_in[2];
    const float* Wq  = (const float*)d_in[3];
    const float* bq  = (const float*)d_in[4];
    const float* Wk  = (const float*)d_in[5];
    const float* bk  = (const float*)d_in[6];
    const float* Wv  = (const float*)d_in[7];
    const float* bv  = (const float*)d_in[8];
    const float* qnw = (const float*)d_in[9];
    const float* knw = (const float*)d_in[10];
    const float* Wo  = (const float*)d_in[11];
    const float* bo  = (const float*)d_in[12];
    float* out = (float*)d_out;

    const int BT = in_sizes[0] / D_MODEL;    // 4096
    const int Bb = BT / T_SEQ;               // 2

    float *qp, *kp;
    cudaGetSymbolAddress((void**)&qp, g_q);
    cudaGetSymbolAddress((void**)&kp, g_k);
    __nv_bfloat16 *xh, *xl, *wh, *wl, *ah, *al, *qh, *ql, *kh, *kl, *vh, *vl;
    cudaGetSymbolAddress((void**)&xh, g_xh);
    cudaGetSymbolAddress((void**)&xl, g_xl);
    cudaGetSymbolAddress((void**)&wh, g_wh);
    cudaGetSymbolAddress((void**)&wl, g_wl);
    cudaGetSymbolAddress((void**)&ah, g_ah);
    cudaGetSymbolAddress((void**)&al, g_al);
    cudaGetSymbolAddress((void**)&qh, g_qh);
    cudaGetSymbolAddress((void**)&ql, g_ql);
    cudaGetSymbolAddress((void**)&kh, g_kh);
    cudaGetSymbolAddress((void**)&kl, g_kl);
    cudaGetSymbolAddress((void**)&vh, g_vh);
    cudaGetSymbolAddress((void**)&vl, g_vl);

    cudaFuncSetAttribute(gemm_bf16, cudaFuncAttributeMaxDynamicSharedMemorySize, GEMM_SMEM);
    cudaFuncSetAttribute(attn_tc, cudaFuncAttributeMaxDynamicSharedMemorySize, ATTN_SMEM);

    const int nX4 = BT * D_MODEL / 4;
    const int nW4 = D_MODEL * D_MODEL / 4;
    const size_t woff = (size_t)D_MODEL * D_MODEL;

    split_bf16<<<(nX4 + 255) / 256, 256>>>(x, xh, xl, nX4);
    dim3 ws((nW4 + 255) / 256, 4);
    split_bf16_w<<<ws, 256>>>(Wq, Wk, Wv, Wo, wh, wl, nW4);

    // fused QKV: bz 0 -> Q fp32, bz 1 -> K fp32, bz 2 -> V bf16 hi/lo
    dim3 gq(D_MODEL / TN, BT / TM, 3);   // (8, 32, 3)
    gemm_bf16<<<gq, 256, GEMM_SMEM>>>(xh, xl, wh, wl,
                                      bq, qp, bk, kp, bv, vh, vl,
                                      BT, D_MODEL, D_MODEL);

    const float qscale = 0.08838834764831845f * 1.4426950408889634f;
    dim3 rn(BT, 2);
    rmsnorm_rope_bf<<<rn, 256>>>(qp, kp, qnw, knw, cosb, sinb,
                                 qh, ql, kh, kl, qscale);

    dim3 adim(T_SEQ / AQ, N_HEADS, Bb);   // (32, 16, 2)
    attn_tc<<<adim, 128, ATTN_SMEM>>>(qh, ql, kh, kl, vh, vl, ah, al);

    dim3 go(D_MODEL / TN, BT / TM, 1);
    gemm_bf16<<<go, 256, GEMM_SMEM>>>(ah, al, wh + 3 * woff, wl + 3 * woff,
                                      bo, out, bo, out, bo, (__nv_bfloat16*)nullptr,
                                      (__nv_bfloat16*)nullptr,
                                      BT, D_MODEL, D_MODEL);
}

// round 17
// speedup vs baseline: 2.0568x; 1.5414x over previous
#include <cuda_runtime.h>
#include <cuda_bf16.h>
#include <cstdint>
#include <math.h>

#define D_MODEL 2048
#define T_SEQ   2048
#define N_HEADS 16
#define D_HEAD  128
#define BT_MAX  4096   // B=2 * T=2048

// ---------------- scratch (device globals; allocation-free) ----------------
__device__ float g_q[(size_t)BT_MAX * D_MODEL];
__device__ float g_k[(size_t)BT_MAX * D_MODEL];

__device__ __nv_bfloat16 g_xh[(size_t)BT_MAX * D_MODEL];
__device__ __nv_bfloat16 g_xl[(size_t)BT_MAX * D_MODEL];
__device__ __nv_bfloat16 g_wh[(size_t)4 * D_MODEL * D_MODEL];  // Wq,Wk,Wv,Wo hi
__device__ __nv_bfloat16 g_wl[(size_t)4 * D_MODEL * D_MODEL];  // lo
__device__ __nv_bfloat16 g_ah[(size_t)BT_MAX * D_MODEL];       // attn out hi
__device__ __nv_bfloat16 g_al[(size_t)BT_MAX * D_MODEL];

__device__ __nv_bfloat16 g_qh[(size_t)BT_MAX * D_MODEL];       // Q hi (scaled)
__device__ __nv_bfloat16 g_ql[(size_t)BT_MAX * D_MODEL];
__device__ __nv_bfloat16 g_kh[(size_t)BT_MAX * D_MODEL];       // K hi
__device__ __nv_bfloat16 g_kl[(size_t)BT_MAX * D_MODEL];
__device__ __nv_bfloat16 g_vh[(size_t)BT_MAX * D_MODEL];       // V hi [b*t, 2048]
__device__ __nv_bfloat16 g_vl[(size_t)BT_MAX * D_MODEL];

__device__ __forceinline__ uint32_t smem_u32(const void* p) {
    uint32_t a;
    asm("{ .reg .u64 t; cvta.to.shared.u64 t, %1; cvt.u32.u64 %0, t; }" : "=r"(a) : "l"(p));
    return a;
}

__device__ __forceinline__ void mma_bf16(float* c, uint32_t a0, uint32_t a1,
                                         uint32_t a2, uint32_t a3,
                                         uint32_t b0, uint32_t b1) {
    asm volatile(
        "mma.sync.aligned.m16n8k16.row.col.f32.bf16.bf16.f32 "
        "{%0,%1,%2,%3}, {%4,%5,%6,%7}, {%8,%9}, {%0,%1,%2,%3};"
        : "+f"(c[0]), "+f"(c[1]), "+f"(c[2]), "+f"(c[3])
        : "r"(a0), "r"(a1), "r"(a2), "r"(a3), "r"(b0), "r"(b1));
}

#define LDSM4(r, a) asm volatile(                                                  \
    "ldmatrix.sync.aligned.m8n8.x4.shared.b16 {%0,%1,%2,%3}, [%4];"                \
    : "=r"((r)[0]), "=r"((r)[1]), "=r"((r)[2]), "=r"((r)[3]) : "r"(a))

#define LDSM4T(r, a) asm volatile(                                                 \
    "ldmatrix.sync.aligned.m8n8.x4.trans.shared.b16 {%0,%1,%2,%3}, [%4];"          \
    : "=r"((r)[0]), "=r"((r)[1]), "=r"((r)[2]), "=r"((r)[3]) : "r"(a))

__device__ __forceinline__ float ex2f(float x) {
    float r;
    asm("ex2.approx.f32 %0, %1;" : "=f"(r) : "f"(x));
    return r;
}

// ---------------- split fp32 -> bf16 hi + bf16 lo ----------------
__global__ __launch_bounds__(256) void split_bf16(
    const float* __restrict__ src, __nv_bfloat16* __restrict__ hi,
    __nv_bfloat16* __restrict__ lo, int n4)
{
    int i = blockIdx.x * 256 + threadIdx.x;
    if (i >= n4) return;
    float4 v = ((const float4*)src)[i];
    __nv_bfloat16 h0 = __float2bfloat16(v.x);
    __nv_bfloat16 h1 = __float2bfloat16(v.y);
    __nv_bfloat16 h2 = __float2bfloat16(v.z);
    __nv_bfloat16 h3 = __float2bfloat16(v.w);
    __nv_bfloat16 l0 = __float2bfloat16(v.x - __bfloat162float(h0));
    __nv_bfloat16 l1 = __float2bfloat16(v.y - __bfloat162float(h1));
    __nv_bfloat16 l2 = __float2bfloat16(v.z - __bfloat162float(h2));
    __nv_bfloat16 l3 = __float2bfloat16(v.w - __bfloat162float(h3));
    __nv_bfloat162* hp = (__nv_bfloat162*)(hi + (size_t)i * 4);
    __nv_bfloat162* lp = (__nv_bfloat162*)(lo + (size_t)i * 4);
    hp[0] = __nv_bfloat162(h0, h1); hp[1] = __nv_bfloat162(h2, h3);
    lp[0] = __nv_bfloat162(l0, l1); lp[1] = __nv_bfloat162(l2, l3);
}

// merged weight split: blockIdx.y selects which W
__global__ __launch_bounds__(256) void split_bf16_w(
    const float* __restrict__ w0, const float* __restrict__ w1,
    const float* __restrict__ w2, const float* __restrict__ w3,
    __nv_bfloat16* __restrict__ hi, __nv_bfloat16* __restrict__ lo, int n4)
{
    int i = blockIdx.x * 256 + threadIdx.x;
    if (i >= n4) return;
    int y = blockIdx.y;
    const float* src = (y == 0) ? w0 : (y == 1) ? w1 : (y == 2) ? w2 : w3;
    size_t off = (size_t)y * n4;
    float4 v = ((const float4*)src)[i];
    __nv_bfloat16 h0 = __float2bfloat16(v.x);
    __nv_bfloat16 h1 = __float2bfloat16(v.y);
    __nv_bfloat16 h2 = __float2bfloat16(v.z);
    __nv_bfloat16 h3 = __float2bfloat16(v.w);
    __nv_bfloat16 l0 = __float2bfloat16(v.x - __bfloat162float(h0));
    __nv_bfloat16 l1 = __float2bfloat16(v.y - __bfloat162float(h1));
    __nv_bfloat16 l2 = __float2bfloat16(v.z - __bfloat162float(h2));
    __nv_bfloat16 l3 = __float2bfloat16(v.w - __bfloat162float(h3));
    __nv_bfloat162* hp = (__nv_bfloat162*)(hi + (off + i) * 4);
    __nv_bfloat162* lp = (__nv_bfloat162*)(lo + (off + i) * 4);
    hp[0] = __nv_bfloat162(h0, h1); hp[1] = __nv_bfloat162(h2, h3);
    lp[0] = __nv_bfloat162(l0, l1); lp[1] = __nv_bfloat162(l2, l3);
}

// ---------------- 3xBF16 GEMM, CTA 128x256, warp tile 64x64 ----------------
// bz==2 writes bf16 hi/lo (V path); otherwise fp32.
#define TM 128
#define TN 256
#define TKF 32
#define BSTR 40
#define A_REG (TM * BSTR)              // 5120
#define B_REG (TN * BSTR)              // 10240
#define STAGE_E (2 * A_REG + 2 * B_REG)  // 30720 elems
#define GSTAGES 3
#define GEMM_SMEM (GSTAGES * STAGE_E * 2)  // 184320 B

__global__ __launch_bounds__(256) void gemm_bf16(
    const __nv_bfloat16* __restrict__ Ah, const __nv_bfloat16* __restrict__ Al,
    const __nv_bfloat16* __restrict__ Wh, const __nv_bfloat16* __restrict__ Wl,
    const float* __restrict__ bias0, float* __restrict__ C0,
    const float* __restrict__ bias1, float* __restrict__ C1,
    const float* __restrict__ bias2,
    __nv_bfloat16* __restrict__ Vh, __nv_bfloat16* __restrict__ Vl,
    int M, int N, int K)
{
    extern __shared__ __nv_bfloat16 smem[];
    const int tid = threadIdx.x;
    const int bz = blockIdx.z;
    const __nv_bfloat16* Bh = Wh + (size_t)bz * D_MODEL * D_MODEL;
    const __nv_bfloat16* Bl = Wl + (size_t)bz * D_MODEL * D_MODEL;
    const float* bia = (bz == 0) ? bias0 : (bz == 1) ? bias1 : bias2;
    float*       C   = (bz == 0) ? C0 : C1;

    const int m0 = blockIdx.y * TM;
    const int n0 = blockIdx.x * TN;
    const int NTILES = K / TKF;   // 64

    const uint32_t sbase = smem_u32(smem);

    // ---- load mapping: 3072 16B-chunks per stage, 12 per thread ----
    const __nv_bfloat16* gsrc[12];
    uint32_t soff[12];
#pragma unroll
    for (int i = 0; i < 12; i++) {
        int c = tid + i * 256;
        if (c < 1024) {
            int m = c & 511, row = m >> 2, j = m & 3;
            const __nv_bfloat16* bp = (c < 512) ? Ah : Al;
            gsrc[i] = bp + (size_t)(m0 + row) * K + j * 8;
            soff[i] = (uint32_t)(((c < 512) ? 0 : A_REG) + row * BSTR + j * 8) * 2u;
        } else {
            int cb = c - 1024;
            int m = cb & 1023, row = m >> 2, j = m & 3;
            const __nv_bfloat16* bp = (cb < 1024) ? Bh : Bl;
            gsrc[i] = bp + (size_t)(n0 + row) * K + j * 8;
            soff[i] = (uint32_t)(2 * A_REG + ((cb < 1024) ? 0 : B_REG)
                     + row * BSTR + j * 8) * 2u;
        }
    }

#define LOAD_TILE(t, s) do {                                                     \
        uint32_t _sb = sbase + (uint32_t)((s) * STAGE_E) * 2u;                   \
        size_t _go = (size_t)(t) * TKF;                                          \
        _Pragma("unroll")                                                        \
        for (int _i = 0; _i < 12; _i++) {                                        \
            asm volatile("cp.async.cg.shared.global [%0], [%1], 16;"             \
                :: "r"(_sb + soff[_i]), "l"(gsrc[_i] + _go));                    \
        } } while (0)

    const int warp = tid >> 5, lane = tid & 31;
    const int wm = (warp >> 2) * 64, wn = (warp & 3) * 64;
    const int g = lane >> 2, tg = lane & 3;

    const uint32_t aLane = (uint32_t)((wm + (lane & 15)) * BSTR + (lane >> 4) * 8) * 2u;
    const int bnrow = wn + (lane & 7) + ((lane & 16) ? 8 : 0);
    const uint32_t bLane = (uint32_t)(2 * A_REG + bnrow * BSTR + ((lane & 8) ? 8 : 0)) * 2u;

    float c[4][8][4];
#pragma unroll
    for (int mi = 0; mi < 4; mi++)
#pragma unroll
        for (int ni = 0; ni < 8; ni++)
#pragma unroll
            for (int r = 0; r < 4; r++) c[mi][ni][r] = 0.f;

    LOAD_TILE(0, 0);
    asm volatile("cp.async.commit_group;" ::: "memory");
    LOAD_TILE(1, 1);
    asm volatile("cp.async.commit_group;" ::: "memory");

    for (int kt = 0; kt < NTILES; kt++) {
        asm volatile("cp.async.wait_group 1;" ::: "memory");
        __syncthreads();

        int lt = kt + 2;
        if (lt < NTILES) LOAD_TILE(lt, lt % GSTAGES);
        asm volatile("cp.async.commit_group;" ::: "memory");

        const uint32_t stb = sbase + (uint32_t)((kt % GSTAGES) * STAGE_E) * 2u;
        const uint32_t aB = stb + aLane;
        const uint32_t bB = stb + bLane;

#pragma unroll
        for (int ks = 0; ks < 2; ks++) {
            uint32_t ah[4][4], al[4][4];
#pragma unroll
            for (int mi = 0; mi < 4; mi++) {
                uint32_t ad = aB + (uint32_t)(mi * 16 * BSTR + ks * 16) * 2u;
                LDSM4(ah[mi], ad);
                LDSM4(al[mi], ad + (uint32_t)A_REG * 2u);
            }
#pragma unroll
            for (int p = 0; p < 4; p++) {
                uint32_t bd = bB + (uint32_t)(p * 16 * BSTR + ks * 16) * 2u;
                uint32_t bh[4], bl[4];
                LDSM4(bh, bd);
                LDSM4(bl, bd + (uint32_t)B_REG * 2u);
#pragma unroll
                for (int mi = 0; mi < 4; mi++) {
#pragma unroll
                    for (int hf = 0; hf < 2; hf++) {
                        float* cc = c[mi][2 * p + hf];
                        mma_bf16(cc, ah[mi][0], ah[mi][1], ah[mi][2], ah[mi][3],
                                 bl[2 * hf], bl[2 * hf + 1]);
                        mma_bf16(cc, al[mi][0], al[mi][1], al[mi][2], al[mi][3],
                                 bh[2 * hf], bh[2 * hf + 1]);
                        mma_bf16(cc, ah[mi][0], ah[mi][1], ah[mi][2], ah[mi][3],
                                 bh[2 * hf], bh[2 * hf + 1]);
                    }
                }
            }
        }
    }

    // ---- epilogue ----
#pragma unroll
    for (int ni = 0; ni < 8; ni++) {
        int col = n0 + wn + ni * 8 + 2 * tg;
        float2 bb = *(const float2*)(bia + col);
#pragma unroll
        for (int mi = 0; mi < 4; mi++) {
            int row = m0 + wm + mi * 16 + g;
            float o00 = c[mi][ni][0] + bb.x, o01 = c[mi][ni][1] + bb.y;
            float o10 = c[mi][ni][2] + bb.x, o11 = c[mi][ni][3] + bb.y;
            if (bz == 2) {
                __nv_bfloat162 h0 = __floats2bfloat162_rn(o00, o01);
                __nv_bfloat162 l0 = __floats2bfloat162_rn(
                    o00 - __bfloat162float(h0.x), o01 - __bfloat162float(h0.y));
                __nv_bfloat162 h1 = __floats2bfloat162_rn(o10, o11);
                __nv_bfloat162 l1 = __floats2bfloat162_rn(
                    o10 - __bfloat162float(h1.x), o11 - __bfloat162float(h1.y));
                *(__nv_bfloat162*)(Vh + (size_t)row * N + col) = h0;
                *(__nv_bfloat162*)(Vl + (size_t)row * N + col) = l0;
                *(__nv_bfloat162*)(Vh + (size_t)(row + 8) * N + col) = h1;
                *(__nv_bfloat162*)(Vl + (size_t)(row + 8) * N + col) = l1;
            } else {
                float2 w0 = make_float2(o00, o01), w1 = make_float2(o10, o11);
                *(float2*)(C + (size_t)row * N + col) = w0;
                *(float2*)(C + (size_t)(row + 8) * N + col) = w1;
            }
        }
    }
#undef LOAD_TILE
}

// ---------------- fused RMSNorm + RoPE -> bf16 hi/lo; blockIdx.y: 0=Q, 1=K ----------------
__global__ __launch_bounds__(256) void rmsnorm_rope_bf(
    const float* __restrict__ qsrc, const float* __restrict__ ksrc,
    const float* __restrict__ qw, const float* __restrict__ kw,
    const float* __restrict__ cosb, const float* __restrict__ sinb,
    __nv_bfloat16* __restrict__ qoh, __nv_bfloat16* __restrict__ qol,
    __nv_bfloat16* __restrict__ koh, __nv_bfloat16* __restrict__ kol,
    float qscale)
{
    const int which = blockIdx.y;
    const float* hsrc = which ? ksrc : qsrc;
    const float* w    = which ? kw   : qw;
    __nv_bfloat16* oh = which ? koh  : qoh;
    __nv_bfloat16* ol = which ? kol  : qol;
    const float outscale = which ? 1.0f : qscale;

    const int row = blockIdx.x;
    const int t = row & (T_SEQ - 1);
    const float* hp = hsrc + (size_t)row * D_MODEL;
    const float* cp = cosb + (size_t)t * D_MODEL;
    const float* sp = sinb + (size_t)t * D_MODEL;
    const int tid = threadIdx.x;

    float4 vals[2];
    float ss = 0.f;
#pragma unroll
    for (int i = 0; i < 2; i++) {
        float4 v = ((const float4*)hp)[tid + i * 256];
        vals[i] = v;
        ss += v.x * v.x + v.y * v.y + v.z * v.z + v.w * v.w;
    }
#pragma unroll
    for (int o = 16; o > 0; o >>= 1) ss += __shfl_xor_sync(0xffffffffu, ss, o);
    __shared__ float red[8];
    __shared__ float s_inv;
    if ((tid & 31) == 0) red[tid >> 5] = ss;
    __syncthreads();
    if (tid == 0) {
        float tot = 0.f;
#pragma unroll
        for (int i = 0; i < 8; i++) tot += red[i];
        s_inv = rsqrtf(tot * (1.0f / D_MODEL) + 1e-6f);
    }
    __syncthreads();
    const float inv = s_inv;

#pragma unroll
    for (int i = 0; i < 2; i++) {
        int fi = tid + i * 256;
        float4 v = vals[i];
        float4 wv = ((const float4*)w)[fi];
        float4 c4 = ((const float4*)cp)[fi];
        float4 s4 = ((const float4*)sp)[fi];
        float nx = v.x * inv * wv.x;
        float ny = v.y * inv * wv.y;
        float nz = v.z * inv * wv.z;
        float nw = v.w * inv * wv.w;
        float o0 = (nx * c4.x - ny * s4.x) * outscale;
        float o1 = (ny * c4.y + nx * s4.y) * outscale;
        float o2 = (nz * c4.z - nw * s4.z) * outscale;
        float o3 = (nw * c4.w + nz * s4.w) * outscale;
        __nv_bfloat16 h0 = __float2bfloat16(o0), h1 = __float2bfloat16(o1);
        __nv_bfloat16 h2 = __float2bfloat16(o2), h3 = __float2bfloat16(o3);
        __nv_bfloat16 l0 = __float2bfloat16(o0 - __bfloat162float(h0));
        __nv_bfloat16 l1 = __float2bfloat16(o1 - __bfloat162float(h1));
        __nv_bfloat16 l2 = __float2bfloat16(o2 - __bfloat162float(h2));
        __nv_bfloat16 l3 = __float2bfloat16(o3 - __bfloat162float(h3));
        __nv_bfloat162* hp2 = (__nv_bfloat162*)(oh + (size_t)row * D_MODEL + fi * 4);
        __nv_bfloat162* lp2 = (__nv_bfloat162*)(ol + (size_t)row * D_MODEL + fi * 4);
        hp2[0] = __nv_bfloat162(h0, h1); hp2[1] = __nv_bfloat162(h2, h3);
        lp2[0] = __nv_bfloat162(l0, l1); lp2[1] = __nv_bfloat162(l2, l3);
    }
}

// ---------------- tensor-core flash attention (3xBF16, 2 CTAs/SM) ----------------
// AQ=64, 128 threads. K double-buffered, V single-buffered. V trans via ldmatrix.
#define AQ 64
#define AK 64
#define KSTR 136
#define K_ELEMS (AK * KSTR)                  // 8704
#define KSTAGE (2 * K_ELEMS)                 // hi+lo, 17408 elems
#define V_BASE (2 * KSTAGE)                  // after 2 K stages
#define ATTN_ELEMS (V_BASE + 2 * K_ELEMS)    // 52224 elems
#define ATTN_SMEM (ATTN_ELEMS * 2)           // 104448 B

__global__ __launch_bounds__(128, 2) void attn_tc(
    const __nv_bfloat16* __restrict__ Qh, const __nv_bfloat16* __restrict__ Ql,
    const __nv_bfloat16* __restrict__ Kh, const __nv_bfloat16* __restrict__ Kl,
    const __nv_bfloat16* __restrict__ Vh, const __nv_bfloat16* __restrict__ Vl,
    __nv_bfloat16* __restrict__ Oh, __nv_bfloat16* __restrict__ Ol)
{
    extern __shared__ __nv_bfloat16 asm_s[];
    const int tid = threadIdx.x, warp = tid >> 5, lane = tid & 31;
    const int g = lane >> 2, tg = lane & 3;
    const int h = blockIdx.y, b = blockIdx.z;
    const int q0 = blockIdx.x * AQ;
    const size_t tokbase = (size_t)b * T_SEQ;
    const uint32_t sbase = smem_u32(asm_s);
    const int NT = T_SEQ / AK;   // 32

    // K fragment lane base (non-trans): rows = token
    const int lrow16 = (lane & 7) + ((lane & 16) ? 8 : 0);
    const uint32_t kLane = (uint32_t)(lrow16 * KSTR + ((lane & 8) ? 8 : 0)) * 2u;
    // V fragment lane base (trans): rows = token (lane&15), col half by lane&16
    const uint32_t vLane = (uint32_t)((lane & 15) * KSTR + ((lane & 16) ? 8 : 0)) * 2u
                         + (uint32_t)V_BASE * 2u;

    // ---- Q fragments in registers (16 rows per warp) ----
    const int qr = q0 + warp * 16;
    uint32_t qfh[8][4], qfl[8][4];
    {
        const __nv_bfloat16* bh_ = Qh + (tokbase + qr) * D_MODEL + h * D_HEAD;
        const __nv_bfloat16* bl_ = Ql + (tokbase + qr) * D_MODEL + h * D_HEAD;
#pragma unroll
        for (int ks = 0; ks < 8; ks++) {
            int k0 = ks * 16 + 2 * tg;
            qfh[ks][0] = *(const uint32_t*)(bh_ + (size_t)g * D_MODEL + k0);
            qfh[ks][1] = *(const uint32_t*)(bh_ + (size_t)(g + 8) * D_MODEL + k0);
            qfh[ks][2] = *(const uint32_t*)(bh_ + (size_t)g * D_MODEL + k0 + 8);
            qfh[ks][3] = *(const uint32_t*)(bh_ + (size_t)(g + 8) * D_MODEL + k0 + 8);
            qfl[ks][0] = *(const uint32_t*)(bl_ + (size_t)g * D_MODEL + k0);
            qfl[ks][1] = *(const uint32_t*)(bl_ + (size_t)(g + 8) * D_MODEL + k0);
            qfl[ks][2] = *(const uint32_t*)(bl_ + (size_t)g * D_MODEL + k0 + 8);
            qfl[ks][3] = *(const uint32_t*)(bl_ + (size_t)(g + 8) * D_MODEL + k0 + 8);
        }
    }

    float Oacc[16][4];
#pragma unroll
    for (int d = 0; d < 16; d++)
#pragma unroll
        for (int r = 0; r < 4; r++) Oacc[d][r] = 0.f;
    float mA = -1e30f, mB = -1e30f, lA = 0.f, lB = 0.f;

    // 2048 chunks per K/V load, 16 per thread (128 threads)
#define LOAD_K(kt, s) do {                                                           \
        uint32_t _sb = sbase + (uint32_t)((s) * KSTAGE) * 2u;                        \
        _Pragma("unroll")                                                            \
        for (int _i = 0; _i < 16; _i++) {                                            \
            int _c = tid + _i * 128;                                                 \
            int _m = _c & 1023; int _row = _m >> 4, _j = _m & 15;                    \
            const __nv_bfloat16* _bp = (_c < 1024) ? Kh : Kl;                        \
            const __nv_bfloat16* _src = _bp + (tokbase + (size_t)(kt) * AK + _row)   \
                                        * D_MODEL + h * D_HEAD + _j * 8;             \
            uint32_t _dst = _sb + (uint32_t)(((_c < 1024) ? 0 : K_ELEMS)             \
                            + _row * KSTR + _j * 8) * 2u;                            \
            asm volatile("cp.async.cg.shared.global [%0], [%1], 16;"                 \
                         :: "r"(_dst), "l"(_src));                                   \
        } } while (0)

#define LOAD_V(kt) do {                                                              \
        uint32_t _sb = sbase + (uint32_t)V_BASE * 2u;                                \
        _Pragma("unroll")                                                            \
        for (int _i = 0; _i < 16; _i++) {                                            \
            int _c = tid + _i * 128;                                                 \
            int _m = _c & 1023; int _row = _m >> 4, _j = _m & 15;                    \
            const __nv_bfloat16* _bp = (_c < 1024) ? Vh : Vl;                        \
            const __nv_bfloat16* _src = _bp + (tokbase + (size_t)(kt) * AK + _row)   \
                                        * D_MODEL + h * D_HEAD + _j * 8;             \
            uint32_t _dst = _sb + (uint32_t)(((_c < 1024) ? 0 : K_ELEMS)             \
                            + _row * KSTR + _j * 8) * 2u;                            \
            asm volatile("cp.async.cg.shared.global [%0], [%1], 16;"                 \
                         :: "r"(_dst), "l"(_src));                                   \
        } } while (0)

    LOAD_K(0, 0);
    asm volatile("cp.async.commit_group;" ::: "memory");

    for (int kt = 0; kt < NT; kt++) {
        __syncthreads();   // all warps done with V buffer + K stage (kt+1)&1
        LOAD_V(kt);
        asm volatile("cp.async.commit_group;" ::: "memory");
        if (kt + 1 < NT) LOAD_K(kt + 1, (kt + 1) & 1);
        asm volatile("cp.async.commit_group;" ::: "memory");   // always (maybe empty)
        asm volatile("cp.async.wait_group 2;" ::: "memory");   // K(kt) ready
        __syncthreads();

        const uint32_t kB = sbase + (uint32_t)((kt & 1) * KSTAGE) * 2u + kLane;

        // ---- S = Q K^T (16 x 64 per warp) ----
        float sf[8][4];
#pragma unroll
        for (int p = 0; p < 4; p++) {
            float acc0[4] = {0.f, 0.f, 0.f, 0.f};
            float acc1[4] = {0.f, 0.f, 0.f, 0.f};
#pragma unroll
            for (int ks = 0; ks < 8; ks++) {
                uint32_t ad = kB + (uint32_t)(p * 16 * KSTR + ks * 16) * 2u;
                uint32_t kh[4], kl[4];
                LDSM4(kh, ad);
                LDSM4(kl, ad + (uint32_t)K_ELEMS * 2u);
                mma_bf16(acc0, qfh[ks][0], qfh[ks][1], qfh[ks][2], qfh[ks][3], kl[0], kl[1]);
                mma_bf16(acc0, qfl[ks][0], qfl[ks][1], qfl[ks][2], qfl[ks][3], kh[0], kh[1]);
                mma_bf16(acc0, qfh[ks][0], qfh[ks][1], qfh[ks][2], qfh[ks][3], kh[0], kh[1]);
                mma_bf16(acc1, qfh[ks][0], qfh[ks][1], qfh[ks][2], qfh[ks][3], kl[2], kl[3]);
                mma_bf16(acc1, qfl[ks][0], qfl[ks][1], qfl[ks][2], qfl[ks][3], kh[2], kh[3]);
                mma_bf16(acc1, qfh[ks][0], qfh[ks][1], qfh[ks][2], qfh[ks][3], kh[2], kh[3]);
            }
#pragma unroll
            for (int r = 0; r < 4; r++) {
                sf[2 * p][r] = acc0[r];
                sf[2 * p + 1][r] = acc1[r];
            }
        }

        // ---- online softmax (exp2 domain; Q pre-scaled by scale*log2e) ----
        float tmA = fmaxf(sf[0][0], sf[0][1]);
        float tmB = fmaxf(sf[0][2], sf[0][3]);
#pragma unroll
        for (int n = 1; n < 8; n++) {
            tmA = fmaxf(tmA, fmaxf(sf[n][0], sf[n][1]));
            tmB = fmaxf(tmB, fmaxf(sf[n][2], sf[n][3]));
        }
        tmA = fmaxf(tmA, __shfl_xor_sync(0xffffffffu, tmA, 1));
        tmA = fmaxf(tmA, __shfl_xor_sync(0xffffffffu, tmA, 2));
        tmB = fmaxf(tmB, __shfl_xor_sync(0xffffffffu, tmB, 1));
        tmB = fmaxf(tmB, __shfl_xor_sync(0xffffffffu, tmB, 2));
        float mAn = fmaxf(mA, tmA), mBn = fmaxf(mB, tmB);
        float corrA = ex2f(mA - mAn), corrB = ex2f(mB - mBn);
        mA = mAn; mB = mBn;

        float sumA = 0.f, sumB = 0.f;
#pragma unroll
        for (int n = 0; n < 8; n++) {
            sf[n][0] = ex2f(sf[n][0] - mA);
            sf[n][1] = ex2f(sf[n][1] - mA);
            sf[n][2] = ex2f(sf[n][2] - mB);
            sf[n][3] = ex2f(sf[n][3] - mB);
            sumA += sf[n][0] + sf[n][1];
            sumB += sf[n][2] + sf[n][3];
        }
        sumA += __shfl_xor_sync(0xffffffffu, sumA, 1);
        sumA += __shfl_xor_sync(0xffffffffu, sumA, 2);
        sumB += __shfl_xor_sync(0xffffffffu, sumB, 1);
        sumB += __shfl_xor_sync(0xffffffffu, sumB, 2);
        lA = lA * corrA + sumA;
        lB = lB * corrB + sumB;

#pragma unroll
        for (int d = 0; d < 16; d++) {
            Oacc[d][0] *= corrA; Oacc[d][1] *= corrA;
            Oacc[d][2] *= corrB; Oacc[d][3] *= corrB;
        }

        // ---- P fragments (hi/lo bf16) ----
        uint32_t pfh[4][4], pfl[4][4];
#pragma unroll
        for (int kv = 0; kv < 4; kv++) {
#pragma unroll
            for (int half = 0; half < 2; half++) {
                int n = 2 * kv + half;
                float p0 = sf[n][0], p1 = sf[n][1], p2 = sf[n][2], p3 = sf[n][3];
                __nv_bfloat162 h01 = __floats2bfloat162_rn(p0, p1);
                __nv_bfloat162 h23 = __floats2bfloat162_rn(p2, p3);
                __nv_bfloat162 l01 = __floats2bfloat162_rn(
                    p0 - __bfloat162float(h01.x), p1 - __bfloat162float(h01.y));
                __nv_bfloat162 l23 = __floats2bfloat162_rn(
                    p2 - __bfloat162float(h23.x), p3 - __bfloat162float(h23.y));
                pfh[kv][0 + 2 * half] = *(uint32_t*)&h01;
                pfh[kv][1 + 2 * half] = *(uint32_t*)&h23;
                pfl[kv][0 + 2 * half] = *(uint32_t*)&l01;
                pfl[kv][1 + 2 * half] = *(uint32_t*)&l23;
            }
        }

        // ---- wait for V, then O += P V (trans ldmatrix) ----
        asm volatile("cp.async.wait_group 1;" ::: "memory");   // V(kt) ready
        __syncthreads();

#pragma unroll
        for (int dp = 0; dp < 8; dp++) {
#pragma unroll
            for (int kv = 0; kv < 4; kv++) {
                uint32_t vbase = sbase + vLane
                               + (uint32_t)(kv * 16 * KSTR + dp * 16) * 2u;
                uint32_t vh[4], vl[4];
                LDSM4T(vh, vbase);
                LDSM4T(vl, vbase + (uint32_t)K_ELEMS * 2u);
                float* oc0 = Oacc[2 * dp];
                float* oc1 = Oacc[2 * dp + 1];
                mma_bf16(oc0, pfh[kv][0], pfh[kv][1], pfh[kv][2], pfh[kv][3], vl[0], vl[1]);
                mma_bf16(oc0, pfl[kv][0], pfl[kv][1], pfl[kv][2], pfl[kv][3], vh[0], vh[1]);
                mma_bf16(oc0, pfh[kv][0], pfh[kv][1], pfh[kv][2], pfh[kv][3], vh[0], vh[1]);
                mma_bf16(oc1, pfh[kv][0], pfh[kv][1], pfh[kv][2], pfh[kv][3], vl[2], vl[3]);
                mma_bf16(oc1, pfl[kv][0], pfl[kv][1], pfl[kv][2], pfl[kv][3], vh[2], vh[3]);
                mma_bf16(oc1, pfh[kv][0], pfh[kv][1], pfh[kv][2], pfh[kv][3], vh[2], vh[3]);
            }
        }
    }

    // ---- finalize: write bf16 hi/lo ----
    float liA = 1.0f / lA, liB = 1.0f / lB;
    const size_t rowA = (tokbase + qr + g) * D_MODEL + h * D_HEAD;
    const size_t rowB = (tokbase + qr + g + 8) * D_MODEL + h * D_HEAD;
#pragma unroll
    for (int d = 0; d < 16; d++) {
        float a0 = Oacc[d][0] * liA, a1 = Oacc[d][1] * liA;
        float b0 = Oacc[d][2] * liB, b1 = Oacc[d][3] * liB;
        __nv_bfloat162 hA = __floats2bfloat162_rn(a0, a1);
        __nv_bfloat162 lAv = __floats2bfloat162_rn(a0 - __bfloat162float(hA.x),
                                                   a1 - __bfloat162float(hA.y));
        __nv_bfloat162 hB = __floats2bfloat162_rn(b0, b1);
        __nv_bfloat162 lBv = __floats2bfloat162_rn(b0 - __bfloat162float(hB.x),
                                                   b1 - __bfloat162float(hB.y));
        *(__nv_bfloat162*)(Oh + rowA + d * 8 + 2 * tg) = hA;
        *(__nv_bfloat162*)(Ol + rowA + d * 8 + 2 * tg) = lAv;
        *(__nv_bfloat162*)(Oh + rowB + d * 8 + 2 * tg) = hB;
        *(__nv_bfloat162*)(Ol + rowB + d * 8 + 2 * tg) = lBv;
    }
#undef LOAD_K
#undef LOAD_V
}

// ---------------- host launch ----------------
extern "C" void kernel_launch(void* const* d_in, const int* in_sizes, int n_in,
                              void* d_out, int out_size)
{
    const float* x   = (const float*)d_in[0];
    const float* cosb= (const float*)d_in[1];
    const float* sinb= (const float*)d_in[2];
    const float* Wq  = (const float*)d_in[3];
    const float* bq  = (const float*)d_in[4];
    const float* Wk  = (const float*)d_in[5];
    const float* bk  = (const float*)d_in[6];
    const float* Wv  = (const float*)d_in[7];
    const float* bv  = (const float*)d_in[8];
    const float* qnw = (const float*)d_in[9];
    const float* knw = (const float*)d_in[10];
    const float* Wo  = (const float*)d_in[11];
    const float* bo  = (const float*)d_in[12];
    float* out = (float*)d_out;

    const int BT = in_sizes[0] / D_MODEL;    // 4096
    const int Bb = BT / T_SEQ;               // 2

    float *qp, *kp;
    cudaGetSymbolAddress((void**)&qp, g_q);
    cudaGetSymbolAddress((void**)&kp, g_k);
    __nv_bfloat16 *xh, *xl, *wh, *wl, *ah, *al, *qh, *ql, *kh, *kl, *vh, *vl;
    cudaGetSymbolAddress((void**)&xh, g_xh);
    cudaGetSymbolAddress((void**)&xl, g_xl);
    cudaGetSymbolAddress((void**)&wh, g_wh);
    cudaGetSymbolAddress((void**)&wl, g_wl);
    cudaGetSymbolAddress((void**)&ah, g_ah);
    cudaGetSymbolAddress((void**)&al, g_al);
    cudaGetSymbolAddress((void**)&qh, g_qh);
    cudaGetSymbolAddress((void**)&ql, g_ql);
    cudaGetSymbolAddress((void**)&kh, g_kh);
    cudaGetSymbolAddress((void**)&kl, g_kl);
    cudaGetSymbolAddress((void**)&vh, g_vh);
    cudaGetSymbolAddress((void**)&vl, g_vl);

    cudaFuncSetAttribute(gemm_bf16, cudaFuncAttributeMaxDynamicSharedMemorySize, GEMM_SMEM);
    cudaFuncSetAttribute(attn_tc, cudaFuncAttributeMaxDynamicSharedMemorySize, ATTN_SMEM);

    const int nX4 = BT * D_MODEL / 4;
    const int nW4 = D_MODEL * D_MODEL / 4;
    const size_t woff = (size_t)D_MODEL * D_MODEL;

    split_bf16<<<(nX4 + 255) / 256, 256>>>(x, xh, xl, nX4);
    dim3 ws((nW4 + 255) / 256, 4);
    split_bf16_w<<<ws, 256>>>(Wq, Wk, Wv, Wo, wh, wl, nW4);

    // fused QKV: bz 0 -> Q fp32, bz 1 -> K fp32, bz 2 -> V bf16 hi/lo
    dim3 gq(D_MODEL / TN, BT / TM, 3);   // (8, 32, 3)
    gemm_bf16<<<gq, 256, GEMM_SMEM>>>(xh, xl, wh, wl,
                                      bq, qp, bk, kp, bv, vh, vl,
                                      BT, D_MODEL, D_MODEL);

    const float qscale = 0.08838834764831845f * 1.4426950408889634f;
    dim3 rn(BT, 2);
    rmsnorm_rope_bf<<<rn, 256>>>(qp, kp, qnw, knw, cosb, sinb,
                                 qh, ql, kh, kl, qscale);

    dim3 adim(T_SEQ / AQ, N_HEADS, Bb);   // (32, 16, 2)
    attn_tc<<<adim, 128, ATTN_SMEM>>>(qh, ql, kh, kl, vh, vl, ah, al);

    dim3 go(D_MODEL / TN, BT / TM, 1);
    gemm_bf16<<<go, 256, GEMM_SMEM>>>(ah, al, wh + 3 * woff, wl + 3 * woff,
                                      bo, out, bo, out, bo, (__nv_bfloat16*)nullptr,
                                      (__nv_bfloat16*)nullptr,
                                      BT, D_MODEL, D_MODEL);
}